// round 8
// baseline (speedup 1.0000x reference)
#include <cuda_runtime.h>
#include <cuda.h>
#include <cuda_bf16.h>
#include <math.h>
#include <cstdint>

// arch guard: tcgen05 only exists on the sm_103a-specific compilation pass
#if !defined(__CUDA_ARCH__) || defined(__CUDA_ARCH_FEAT_SM103_ALL) || \
    (defined(__CUDA_ARCH_SPECIFIC__) && (__CUDA_ARCH_SPECIFIC__ == 1030))
#define USE_TCG 1
#else
#define USE_TCG 0
#endif

// Problem constants
#define Bb 4
#define Ss 1024
#define Dd 1024
#define Hh 2048
#define Ee 8
#define Nn (Bb*Ss)      // 4096 tokens
#define Rr (2*Nn)       // 8192 expert-rows (top-2)

// Output layout (concatenated float32)
#define OUT_FINAL 0
#define OUT_GATE  (Nn*Dd)
#define OUT_ELOG  (OUT_GATE + Nn*Ee)
#define OUT_ROUT  (OUT_ELOG + Ee*Bb)

// ---------------- device scratch ---------------------------------------
__device__ int   g_count[Ee];
__device__ int   g_offset[Ee];
__device__ int   g_cursor[Ee];
__device__ int   g_sel[Nn*2];
__device__ float g_selw[Nn*2];
__device__ int   g_row_token[Rr];
__device__ float g_row_weight[Rr];
__device__ int   g_slot_row[Nn*2];
__device__ float g_v[Ee*Hh];
__device__ float g_cls_delta[Ee*Bb];
// pre-split hi/lo bf16 operands
__device__ __nv_bfloat16 g_xh[(size_t)Nn*Dd];
__device__ __nv_bfloat16 g_xl[(size_t)Nn*Dd];
__device__ __nv_bfloat16 g_w1h[(size_t)Ee*Hh*Dd];
__device__ __nv_bfloat16 g_w1l[(size_t)Ee*Hh*Dd];
__device__ __nv_bfloat16 g_w3h[(size_t)Ee*Hh*Dd];
__device__ __nv_bfloat16 g_w3l[(size_t)Ee*Hh*Dd];
__device__ __nv_bfloat16 g_w2h[(size_t)Ee*Dd*Hh];
__device__ __nv_bfloat16 g_w2l[(size_t)Ee*Dd*Hh];
__device__ __nv_bfloat16 g_hh[(size_t)Rr*Hh];
__device__ __nv_bfloat16 g_hl[(size_t)Rr*Hh];

// ================= inline PTX helpers =====================================
__device__ __forceinline__ uint32_t smem_to_u32(const void* p) {
    uint32_t a;
    asm("{ .reg .u64 t; cvta.to.shared.u64 t, %1; cvt.u32.u64 %0, t; }"
        : "=r"(a) : "l"(p));
    return a;
}
#define CP16(dst, src) \
    asm volatile("cp.async.cg.shared.global [%0], [%1], 16;" \
                 :: "r"((uint32_t)(dst)), "l"(src) : "memory")
#define CP_COMMIT() asm volatile("cp.async.commit_group;" ::: "memory")
#define CP_WAIT0()  asm volatile("cp.async.wait_group 0;" ::: "memory")
#define CP_WAIT1()  asm volatile("cp.async.wait_group 1;" ::: "memory")
#define TMA_LOAD_3D(smem_addr, tmap, cx, cy, cz, mbar) \
    asm volatile( \
        "cp.async.bulk.tensor.3d.shared::cta.global.tile.mbarrier::complete_tx::bytes " \
        "[%0], [%1, {%2, %3, %4}], [%5];" \
        :: "r"((uint32_t)(smem_addr)), "l"(tmap), "r"((int32_t)(cx)), \
           "r"((int32_t)(cy)), "r"((int32_t)(cz)), "r"((uint32_t)(mbar)) \
        : "memory")
#define MBAR_EXPECT_TX(mbar, bytes) \
    asm volatile("mbarrier.arrive.expect_tx.shared.b64 _, [%0], %1;" \
                 :: "r"((uint32_t)(mbar)), "r"((uint32_t)(bytes)) : "memory")

#if USE_TCG
__device__ __forceinline__ uint32_t elect_one_pred() {
    uint32_t pred;
    asm volatile("{\n\t.reg .pred p;\n\telect.sync _|p, 0xFFFFFFFF;\n\t"
                 "selp.b32 %0, 1, 0, p;\n\t}" : "=r"(pred));
    return pred;
}
#define TCG_ALLOC(smem_addr, n) \
    asm volatile("tcgen05.alloc.cta_group::1.sync.aligned.shared::cta.b32 [%0], %1;" \
                 :: "r"((uint32_t)(smem_addr)), "r"((uint32_t)(n)) : "memory")
#define TCG_DEALLOC(tmem, n) \
    asm volatile("tcgen05.dealloc.cta_group::1.sync.aligned.b32 %0, %1;" \
                 :: "r"(tmem), "r"((uint32_t)(n)))
#define TCG_RELINQ() \
    asm volatile("tcgen05.relinquish_alloc_permit.cta_group::1.sync.aligned;")
#define TCG_COMMIT(mbar) \
    asm volatile("tcgen05.commit.cta_group::1.mbarrier::arrive::one.shared::cluster.b64 [%0];" \
                 :: "r"((uint32_t)(mbar)) : "memory")
#define TCG_FENCE_AFTER() \
    asm volatile("tcgen05.fence::after_thread_sync;" ::: "memory")
#define TCG_WAIT_LD() \
    asm volatile("tcgen05.wait::ld.sync.aligned;" ::: "memory")
#define FENCE_ASYNC_SHARED() \
    asm volatile("fence.proxy.async.shared::cta;" ::: "memory")
#define MBAR_INIT(mbar, cnt) \
    asm volatile("mbarrier.init.shared.b64 [%0], %1;" \
                 :: "r"((uint32_t)(mbar)), "r"((uint32_t)(cnt)) : "memory")
#define MBAR_WAIT(mbar, parity) do { \
    uint32_t _m = (uint32_t)(mbar); uint32_t _p = (uint32_t)(parity); uint32_t _d; \
    asm volatile("{\n\t.reg .pred p;\n\t" \
        "mbarrier.try_wait.parity.acquire.cta.shared::cta.b64 p, [%1], %2;\n\t" \
        "selp.b32 %0, 1, 0, p;\n\t}" : "=r"(_d) : "r"(_m), "r"(_p) : "memory"); \
    if (!_d) { \
        asm volatile("{\n\t.reg .pred P1;\n\t" \
            "WL_%=:\n\t" \
            "mbarrier.try_wait.parity.acquire.cta.shared::cta.b64 P1, [%0], %1, 0x989680;\n\t" \
            "@P1 bra.uni WD_%=;\n\t" \
            "bra.uni WL_%=;\n\t" \
            "WD_%=:\n\t}" :: "r"(_m), "r"(_p) : "memory"); \
    } \
} while (0)
#define TCG_LD_X32(r, tm) \
    asm volatile("tcgen05.ld.sync.aligned.32x32b.x32.b32 " \
        "{%0, %1, %2, %3, %4, %5, %6, %7, %8, %9, %10, %11, %12, %13, %14, %15, " \
        " %16, %17, %18, %19, %20, %21, %22, %23, %24, %25, %26, %27, %28, %29, %30, %31}, [%32];" \
        : "=r"((r)[0]), "=r"((r)[1]), "=r"((r)[2]), "=r"((r)[3]), \
          "=r"((r)[4]), "=r"((r)[5]), "=r"((r)[6]), "=r"((r)[7]), \
          "=r"((r)[8]), "=r"((r)[9]), "=r"((r)[10]), "=r"((r)[11]), \
          "=r"((r)[12]), "=r"((r)[13]), "=r"((r)[14]), "=r"((r)[15]), \
          "=r"((r)[16]), "=r"((r)[17]), "=r"((r)[18]), "=r"((r)[19]), \
          "=r"((r)[20]), "=r"((r)[21]), "=r"((r)[22]), "=r"((r)[23]), \
          "=r"((r)[24]), "=r"((r)[25]), "=r"((r)[26]), "=r"((r)[27]), \
          "=r"((r)[28]), "=r"((r)[29]), "=r"((r)[30]), "=r"((r)[31]) \
        : "r"(tm))

__device__ __forceinline__ void mma_f16_ss(uint32_t d, uint64_t a, uint64_t b,
                                           uint32_t idesc, bool en) {
    uint32_t e = en ? 1u : 0u;
    asm volatile("{\n\t.reg .pred p;\n\tsetp.ne.u32 p, %5, 0;\n\t"
        "tcgen05.mma.cta_group::1.kind::f16 [%0], %1, %2, %3, {%4, %4, %4, %4}, p;\n\t}"
        :: "r"(d), "l"(a), "l"(b), "r"(idesc), "r"(0u), "r"(e) : "memory");
}

// SW128 smem descriptor: layout=2, version=1, SBO=64, LBO=1
static __device__ __forceinline__ uint64_t make_desc(uint32_t addr) {
    return ((uint64_t)2 << 61) | ((uint64_t)1 << 46) | ((uint64_t)64 << 32) |
           ((uint64_t)1 << 16) | ((uint64_t)(addr >> 4) & 0x3FFF);
}
#endif // USE_TCG

// idesc: dtype F32, a/b BF16, M=128 (8<<24), N=128 (16<<17)
#define IDESC_128x128 (0x490u | (16u << 17) | (8u << 24))

// GEMM tile constants
#define BM 128
#define BN 128
#define BK 64
#define BM2 256                       // ffn2 rows per CTA
// SW128 tile offset for a 128x64 bf16 tile (single atom column)
__device__ __forceinline__ uint32_t tile_off(int r, int c) {
    uint32_t off = (uint32_t)((r >> 3) * 1024 + (r & 7) * 128 + c * 2);
    return off ^ ((off >> 3) & 0x70u);
}

// SMEM maps (double-buffered, occ 1)
// header: tmem @0, mma_mbar[2] @8/@16, tma_mbar[2] @24/@32, row idx @64
#define T_SZ 16384
#define HDR 2048
#define F1_STG (6*T_SZ)               // AH AL B1H B1L B3H B3L
#define FFN1_SMEM (HDR + 2*F1_STG)    // 198656
#define F2_STG (6*T_SZ)               // A0H A0L A1H A1L WH WL
#define FFN2_SMEM (HDR + 2*F2_STG)    // 198656

// ---------------- init ----------------------------------------------------
__global__ void init_kernel(float* __restrict__ out) {
    size_t i = (size_t)blockIdx.x * blockDim.x + threadIdx.x;
    size_t stride = (size_t)gridDim.x * blockDim.x;
    for (size_t j = i; j < (size_t)Nn * Dd; j += stride)
        out[OUT_FINAL + j] = 0.0f;
    if (blockIdx.x == 0) {
        if (threadIdx.x < Ee) { g_count[threadIdx.x] = 0; g_cursor[threadIdx.x] = 0; }
        if (threadIdx.x < Ee * Bb) g_cls_delta[threadIdx.x] = 0.0f;
    }
}

// ---------------- fp32 -> bf16 hi/lo split --------------------------------
__global__ void split_kernel(const float* __restrict__ s,
                             __nv_bfloat16* __restrict__ hi,
                             __nv_bfloat16* __restrict__ lo, size_t n) {
    size_t i = ((size_t)blockIdx.x * blockDim.x + threadIdx.x) * 8;
    size_t stride = (size_t)gridDim.x * blockDim.x * 8;
    for (; i < n; i += stride) {
        float4 v0 = *(const float4*)(s + i);
        float4 v1 = *(const float4*)(s + i + 4);
        float f[8] = {v0.x, v0.y, v0.z, v0.w, v1.x, v1.y, v1.z, v1.w};
        uint16_t hb[8], lb[8];
        #pragma unroll
        for (int j = 0; j < 8; j++) {
            __nv_bfloat16 h = __float2bfloat16_rn(f[j]);
            __nv_bfloat16 l = __float2bfloat16_rn(f[j] - __bfloat162float(h));
            hb[j] = *(uint16_t*)&h;  lb[j] = *(uint16_t*)&l;
        }
        uint4 hv, lv;
        hv.x = ((uint32_t)hb[1] << 16) | hb[0];
        hv.y = ((uint32_t)hb[3] << 16) | hb[2];
        hv.z = ((uint32_t)hb[5] << 16) | hb[4];
        hv.w = ((uint32_t)hb[7] << 16) | hb[6];
        lv.x = ((uint32_t)lb[1] << 16) | lb[0];
        lv.y = ((uint32_t)lb[3] << 16) | lb[2];
        lv.z = ((uint32_t)lb[5] << 16) | lb[4];
        lv.w = ((uint32_t)lb[7] << 16) | lb[6];
        *(uint4*)(hi + i) = hv;
        *(uint4*)(lo + i) = lv;
    }
}

// ---------------- gating --------------------------------------------------
__global__ void gating_kernel(const float* __restrict__ x,
                              const float* __restrict__ Wg,
                              float* __restrict__ out) {
    int n = blockIdx.x;
    __shared__ float xs[Dd];
    __shared__ float logits[Ee];
    for (int i = threadIdx.x; i < Dd; i += blockDim.x)
        xs[i] = x[(size_t)n * Dd + i];
    __syncthreads();
    int warp = threadIdx.x >> 5, lane = threadIdx.x & 31;
    const float* w = Wg + warp * Dd;
    float s = 0.0f;
    for (int i = lane; i < Dd; i += 32) s += xs[i] * w[i];
    #pragma unroll
    for (int o = 16; o > 0; o >>= 1) s += __shfl_down_sync(0xffffffffu, s, o);
    if (lane == 0) logits[warp] = s;
    __syncthreads();
    if (threadIdx.x == 0) {
        float m = logits[0];
        #pragma unroll
        for (int e = 1; e < Ee; e++) m = fmaxf(m, logits[e]);
        float p[Ee]; float den = 0.0f;
        #pragma unroll
        for (int e = 0; e < Ee; e++) { p[e] = expf(logits[e] - m); den += p[e]; }
        float inv = 1.0f / den;
        #pragma unroll
        for (int e = 0; e < Ee; e++) {
            p[e] *= inv;
            out[OUT_GATE + n * Ee + e] = logits[e];
            out[OUT_ROUT + n * Ee + e] = p[e];
        }
        int i0 = 0;
        #pragma unroll
        for (int e = 1; e < Ee; e++) if (p[e] > p[i0]) i0 = e;
        int i1 = (i0 == 0) ? 1 : 0;
        #pragma unroll
        for (int e = 0; e < Ee; e++) if (e != i0 && p[e] > p[i1]) i1 = e;
        float sw = p[i0] + p[i1];
        g_sel[2*n] = i0;  g_sel[2*n+1] = i1;
        g_selw[2*n] = p[i0] / sw;  g_selw[2*n+1] = p[i1] / sw;
        atomicAdd(&g_count[i0], 1);
        atomicAdd(&g_count[i1], 1);
    }
}

__global__ void scan_kernel() {
    int o = 0;
    for (int e = 0; e < Ee; e++) { g_offset[e] = o; o += g_count[e]; }
}

__global__ void scatter_kernel() {
    int n = blockIdx.x * blockDim.x + threadIdx.x;
    if (n >= Nn) return;
    #pragma unroll
    for (int s = 0; s < 2; s++) {
        int e = g_sel[2*n + s];
        int pos = atomicAdd(&g_cursor[e], 1);
        int r = g_offset[e] + pos;
        g_row_token[r] = n;
        g_row_weight[r] = g_selw[2*n + s];
        g_slot_row[2*n + s] = r;
    }
}

// =================== FFN1: h = silu(X W1^T) * (X W3^T) ====================
// 2-stage pipeline, occ 1: TMA weights + cp.async gathered activations.
__global__ __launch_bounds__(256, 1) void ffn1_mma(
    const __grid_constant__ CUtensorMap t_w1h,
    const __grid_constant__ CUtensorMap t_w1l,
    const __grid_constant__ CUtensorMap t_w3h,
    const __grid_constant__ CUtensorMap t_w3l,
    const float* __restrict__ x,
    const float* __restrict__ W1,
    const float* __restrict__ W3) {
    int e = blockIdx.z;
    int cnt = g_count[e];
    int row0 = blockIdx.x * BM;
    if (row0 >= cnt) return;
    int off = g_offset[e];
    int col0 = blockIdx.y * BN;

#if USE_TCG
    extern __shared__ __align__(1024) char smem[];
    uint32_t sb = smem_to_u32(smem);
    int tid = threadIdx.x, wid = tid >> 5, lid = tid & 31;

    int* tok = (int*)(smem + 64);
    if (tid < 128) tok[tid] = g_row_token[off + min(row0 + tid, cnt - 1)];
    if (wid == 0) TCG_ALLOC(sb + 0, 256);
    if (tid == 0) {
        MBAR_INIT(sb + 8, 1);  MBAR_INIT(sb + 16, 1);   // mma mbar[2]
        MBAR_INIT(sb + 24, 1); MBAR_INIT(sb + 32, 1);   // tma mbar[2]
    }
    __syncthreads();
    uint32_t tmem;
    asm volatile("ld.shared.b32 %0, [%1];" : "=r"(tmem) : "r"(sb + 0));
    if (wid == 0) TCG_RELINQ();

    int lr = tid >> 3;            // 0..31
    int lc = (tid & 7) << 3;      // 0..56 step 8

    const int KCH = Dd / BK;      // 16

    // fill chunk f into stage f&1
    auto fill = [&](int f) {
        int st = f & 1;
        int k0 = f * BK;
        uint32_t sbase = sb + HDR + st * F1_STG;
        if (tid == 0) {
            MBAR_EXPECT_TX(sb + 24 + st * 8, 4 * T_SZ);
            TMA_LOAD_3D(sbase + 2*T_SZ, &t_w1h, k0, col0, e, sb + 24 + st * 8);
            TMA_LOAD_3D(sbase + 3*T_SZ, &t_w1l, k0, col0, e, sb + 24 + st * 8);
            TMA_LOAD_3D(sbase + 4*T_SZ, &t_w3h, k0, col0, e, sb + 24 + st * 8);
            TMA_LOAD_3D(sbase + 5*T_SZ, &t_w3l, k0, col0, e, sb + 24 + st * 8);
        }
        #pragma unroll
        for (int p = 0; p < 4; p++) {
            int r = p * 32 + lr;
            uint32_t so = sbase + tile_off(r, lc);
            size_t ax = (size_t)tok[r] * Dd + k0 + lc;
            CP16(so,        g_xh + ax);
            CP16(so + T_SZ, g_xl + ax);
        }
        CP_COMMIT();
    };

    fill(0);
    for (int c = 0; c < KCH; c++) {
        int st = c & 1;
        if (c + 1 < KCH) {
            if (c + 1 >= 2)
                MBAR_WAIT(sb + 8 + ((c + 1) & 1) * 8, ((((c + 1) >> 1) - 1) & 1));
            fill(c + 1);
            CP_WAIT1();
        } else {
            CP_WAIT0();
        }
        FENCE_ASYNC_SHARED();
        __syncthreads();
        if (wid == 0) {
            MBAR_WAIT(sb + 24 + st * 8, (c >> 1) & 1);
            if (elect_one_pred()) {
                uint32_t sbase = sb + HDR + st * F1_STG;
                uint64_t dAH  = make_desc(sbase);
                uint64_t dAL  = make_desc(sbase + T_SZ);
                uint64_t dB1H = make_desc(sbase + 2*T_SZ);
                uint64_t dB1L = make_desc(sbase + 3*T_SZ);
                uint64_t dB3H = make_desc(sbase + 4*T_SZ);
                uint64_t dB3L = make_desc(sbase + 5*T_SZ);
                #pragma unroll
                for (int s = 0; s < 4; s++) {
                    uint64_t o = (uint64_t)(s * 2);
                    bool first = (c == 0) && (s == 0);
                    mma_f16_ss(tmem + 0,   dAH + o, dB1H + o, IDESC_128x128, !first);
                    mma_f16_ss(tmem + 0,   dAH + o, dB1L + o, IDESC_128x128, true);
                    mma_f16_ss(tmem + 0,   dAL + o, dB1H + o, IDESC_128x128, true);
                    mma_f16_ss(tmem + 128, dAH + o, dB3H + o, IDESC_128x128, !first);
                    mma_f16_ss(tmem + 128, dAH + o, dB3L + o, IDESC_128x128, true);
                    mma_f16_ss(tmem + 128, dAL + o, dB3H + o, IDESC_128x128, true);
                }
                TCG_COMMIT(sb + 8 + st * 8);
            }
        }
    }
    MBAR_WAIT(sb + 8,  ((KCH / 2) - 1) & 1);
    MBAR_WAIT(sb + 16, ((KCH / 2) - 1) & 1);
    TCG_FENCE_AFTER();

    // epilogue: silu(z)*y -> hi/lo bf16 h
    {
        int sub = wid & 3;
        int colh = (wid >> 2) * 64;
        int gr = row0 + sub * 32 + lid;
        bool valid = gr < cnt;
        size_t hbase = (size_t)(off + gr) * Hh + col0;
        #pragma unroll
        for (int half = 0; half < 2; half++) {
            int cc = colh + half * 32;
            uint32_t r1[32], r3[32];
            TCG_LD_X32(r1, tmem + cc);
            TCG_LD_X32(r3, tmem + 128 + cc);
            TCG_WAIT_LD();
            if (valid) {
                #pragma unroll
                for (int j = 0; j < 32; j += 2) {
                    float z0 = __uint_as_float(r1[j]);
                    float z1 = __uint_as_float(r1[j + 1]);
                    float h0 = z0 * (1.0f/(1.0f+__expf(-z0))) * __uint_as_float(r3[j]);
                    float h1 = z1 * (1.0f/(1.0f+__expf(-z1))) * __uint_as_float(r3[j+1]);
                    __nv_bfloat16 h0h = __float2bfloat16_rn(h0);
                    __nv_bfloat16 h1h = __float2bfloat16_rn(h1);
                    __nv_bfloat16 h0l = __float2bfloat16_rn(h0 - __bfloat162float(h0h));
                    __nv_bfloat16 h1l = __float2bfloat16_rn(h1 - __bfloat162float(h1h));
                    uint32_t hp = ((uint32_t)*(uint16_t*)&h1h << 16) | *(uint16_t*)&h0h;
                    uint32_t lp = ((uint32_t)*(uint16_t*)&h1l << 16) | *(uint16_t*)&h0l;
                    *(uint32_t*)(g_hh + hbase + cc + j) = hp;
                    *(uint32_t*)(g_hl + hbase + cc + j) = lp;
                }
            }
        }
    }
    __syncthreads();
    if (wid == 0) TCG_DEALLOC(tmem, 256);
#else
    int tid = threadIdx.x;
    for (int idx = tid; idx < BM * BN; idx += 256) {
        int r = row0 + idx / BN;
        if (r >= cnt) continue;
        int cc = col0 + (idx % BN);
        int tokn = g_row_token[off + r];
        float a1 = 0.0f, a3 = 0.0f;
        for (int k = 0; k < Dd; k++) {
            float xv = x[(size_t)tokn * Dd + k];
            a1 += xv * W1[((size_t)e * Hh + cc) * Dd + k];
            a3 += xv * W3[((size_t)e * Hh + cc) * Dd + k];
        }
        float hv = a1 * (1.0f / (1.0f + __expf(-a1))) * a3;
        __nv_bfloat16 hh = __float2bfloat16_rn(hv);
        g_hh[(size_t)(off + r) * Hh + cc] = hh;
        g_hl[(size_t)(off + r) * Hh + cc] =
            __float2bfloat16_rn(hv - __bfloat162float(hh));
    }
#endif
}

// =================== FFN2: out += (h W2^T) * w =============================
// BM2=256 rows per CTA (two M=128 accumulator sets share W tiles), 2-stage.
__global__ __launch_bounds__(256, 1) void ffn2_mma(
    const __grid_constant__ CUtensorMap t_w2h,
    const __grid_constant__ CUtensorMap t_w2l,
    const float* __restrict__ W2, float* __restrict__ out) {
    int e = blockIdx.z;
    int cnt = g_count[e];
    int row0 = blockIdx.x * BM2;
    if (row0 >= cnt) return;
    int off = g_offset[e];
    int col0 = blockIdx.y * BN;

#if USE_TCG
    extern __shared__ __align__(1024) char smem[];
    uint32_t sb = smem_to_u32(smem);
    int tid = threadIdx.x, wid = tid >> 5, lid = tid & 31;

    int* arow = (int*)(smem + 64);
    if (tid < 256) arow[tid] = off + min(row0 + tid, cnt - 1);
    if (wid == 0) TCG_ALLOC(sb + 0, 256);
    if (tid == 0) {
        MBAR_INIT(sb + 8, 1);  MBAR_INIT(sb + 16, 1);
        MBAR_INIT(sb + 24, 1); MBAR_INIT(sb + 32, 1);
    }
    __syncthreads();
    uint32_t tmem;
    asm volatile("ld.shared.b32 %0, [%1];" : "=r"(tmem) : "r"(sb + 0));
    if (wid == 0) TCG_RELINQ();

    int lr = tid >> 3;
    int lc = (tid & 7) << 3;

    const int KCH = Hh / BK;      // 32

    auto fill = [&](int f) {
        int st = f & 1;
        int k0 = f * BK;
        uint32_t sbase = sb + HDR + st * F2_STG;
        if (tid == 0) {
            MBAR_EXPECT_TX(sb + 24 + st * 8, 2 * T_SZ);
            TMA_LOAD_3D(sbase + 4*T_SZ, &t_w2h, k0, col0, e, sb + 24 + st * 8);
            TMA_LOAD_3D(sbase + 5*T_SZ, &t_w2l, k0, col0, e, sb + 24 + st * 8);
        }
        #pragma unroll
        for (int p = 0; p < 4; p++) {
            int r = p * 32 + lr;
            uint32_t so = sbase + tile_off(r, lc);
            size_t a0 = (size_t)arow[r] * Hh + k0 + lc;
            size_t a1 = (size_t)arow[r + 128] * Hh + k0 + lc;
            CP16(so,          g_hh + a0);
            CP16(so + T_SZ,   g_hl + a0);
            CP16(so + 2*T_SZ, g_hh + a1);
            CP16(so + 3*T_SZ, g_hl + a1);
        }
        CP_COMMIT();
    };

    fill(0);
    for (int c = 0; c < KCH; c++) {
        int st = c & 1;
        if (c + 1 < KCH) {
            if (c + 1 >= 2)
                MBAR_WAIT(sb + 8 + ((c + 1) & 1) * 8, ((((c + 1) >> 1) - 1) & 1));
            fill(c + 1);
            CP_WAIT1();
        } else {
            CP_WAIT0();
        }
        FENCE_ASYNC_SHARED();
        __syncthreads();
        if (wid == 0) {
            MBAR_WAIT(sb + 24 + st * 8, (c >> 1) & 1);
            if (elect_one_pred()) {
                uint32_t sbase = sb + HDR + st * F2_STG;
                uint64_t dA0H = make_desc(sbase);
                uint64_t dA0L = make_desc(sbase + T_SZ);
                uint64_t dA1H = make_desc(sbase + 2*T_SZ);
                uint64_t dA1L = make_desc(sbase + 3*T_SZ);
                uint64_t dBH  = make_desc(sbase + 4*T_SZ);
                uint64_t dBL  = make_desc(sbase + 5*T_SZ);
                #pragma unroll
                for (int s = 0; s < 4; s++) {
                    uint64_t o = (uint64_t)(s * 2);
                    bool first = (c == 0) && (s == 0);
                    mma_f16_ss(tmem + 0,   dA0H + o, dBH + o, IDESC_128x128, !first);
                    mma_f16_ss(tmem + 0,   dA0H + o, dBL + o, IDESC_128x128, true);
                    mma_f16_ss(tmem + 0,   dA0L + o, dBH + o, IDESC_128x128, true);
                    mma_f16_ss(tmem + 128, dA1H + o, dBH + o, IDESC_128x128, !first);
                    mma_f16_ss(tmem + 128, dA1H + o, dBL + o, IDESC_128x128, true);
                    mma_f16_ss(tmem + 128, dA1L + o, dBH + o, IDESC_128x128, true);
                }
                TCG_COMMIT(sb + 8 + st * 8);
            }
        }
    }
    MBAR_WAIT(sb + 8,  ((KCH / 2) - 1) & 1);
    MBAR_WAIT(sb + 16, ((KCH / 2) - 1) & 1);
    TCG_FENCE_AFTER();

    {
        int mblk = wid >> 2;          // which 128-row block / accumulator
        int sub = wid & 3;
        int gr = row0 + mblk * 128 + sub * 32 + lid;
        bool valid = gr < cnt;
        int tokn = valid ? g_row_token[off + gr] : 0;
        float wgt = valid ? g_row_weight[off + gr] : 0.0f;
        float* op = out + OUT_FINAL + (size_t)tokn * Dd + col0;
        uint32_t tbase = tmem + mblk * 128;
        #pragma unroll
        for (int q = 0; q < 4; q++) {
            int cc = q * 32;
            uint32_t r0[32];
            TCG_LD_X32(r0, tbase + cc);
            TCG_WAIT_LD();
            if (valid) {
                #pragma unroll
                for (int j = 0; j < 32; j++)
                    atomicAdd(&op[cc + j], __uint_as_float(r0[j]) * wgt);
            }
        }
    }
    __syncthreads();
    if (wid == 0) TCG_DEALLOC(tmem, 256);
#else
    int tid = threadIdx.x;
    for (int idx = tid; idx < BM2 * BN; idx += 256) {
        int r = row0 + idx / BN;
        if (r >= cnt) continue;
        int cc = col0 + (idx % BN);
        int tokn = g_row_token[off + r];
        float wgt = g_row_weight[off + r];
        float acc = 0.0f;
        for (int k = 0; k < Hh; k++) {
            float hv = __bfloat162float(g_hh[(size_t)(off + r) * Hh + k]) +
                       __bfloat162float(g_hl[(size_t)(off + r) * Hh + k]);
            acc += hv * W2[((size_t)e * Dd + cc) * Hh + k];
        }
        atomicAdd(&out[OUT_FINAL + (size_t)tokn * Dd + cc], acc * wgt);
    }
#endif
}

// ---------------- v[e] = Wc @ W2[e] ---------------------------------------
__global__ void vproj_kernel(const float* __restrict__ W2,
                             const float* __restrict__ Wc) {
    int e = blockIdx.y;
    int hh = blockIdx.x * blockDim.x + threadIdx.x;
    if (hh >= Hh) return;
    const float* W2e = W2 + (size_t)e * Dd * Hh;
    float s = 0.0f;
    for (int d = 0; d < Dd; d++) s += Wc[d] * W2e[(size_t)d * Hh + hh];
    g_v[e * Hh + hh] = s;
}

// ---------------- CLS delta per (batch, slot) ------------------------------
__global__ void cls_kernel() {
    int b = blockIdx.x >> 1;
    int s = blockIdx.x & 1;
    int n = b * Ss;
    int e = g_sel[2*n + s];
    int r = g_slot_row[2*n + s];
    float w = g_selw[2*n + s];
    const __nv_bfloat16* hp = g_hh + (size_t)r * Hh;
    const __nv_bfloat16* lp = g_hl + (size_t)r * Hh;
    const float* vp = g_v + e * Hh;
    float acc = 0.0f;
    for (int i = threadIdx.x; i < Hh; i += blockDim.x)
        acc += (__bfloat162float(hp[i]) + __bfloat162float(lp[i])) * vp[i];
    __shared__ float red[8];
    int lane = threadIdx.x & 31, warp = threadIdx.x >> 5;
    #pragma unroll
    for (int o = 16; o > 0; o >>= 1) acc += __shfl_down_sync(0xffffffffu, acc, o);
    if (lane == 0) red[warp] = acc;
    __syncthreads();
    if (threadIdx.x == 0) {
        float t = 0.0f;
        for (int i = 0; i < (int)(blockDim.x >> 5); i++) t += red[i];
        g_cls_delta[e * Bb + b] = w * t;
    }
}

__global__ void elog_kernel(const float* __restrict__ bc, float* __restrict__ out) {
    int b = threadIdx.x;
    if (b < Bb) {
        float cum = bc[0];
        for (int e = 0; e < Ee; e++) {
            cum += g_cls_delta[e * Bb + b];
            out[OUT_ELOG + e * Bb + b] = cum;
        }
    }
}

// ---------------- host: tensormap encode via driver entry point ------------
typedef CUresult (CUDAAPI *PFN_tme)(
    CUtensorMap*, CUtensorMapDataType, cuuint32_t, void*,
    const cuuint64_t*, const cuuint64_t*, const cuuint32_t*, const cuuint32_t*,
    CUtensorMapInterleave, CUtensorMapSwizzle, CUtensorMapL2promotion,
    CUtensorMapFloatOOBfill);

static void encode_w(PFN_tme enc, CUtensorMap* m, void* base,
                     uint64_t d0, uint64_t d1, uint64_t d2) {
    cuuint64_t dims[3] = {d0, d1, d2};
    cuuint64_t strides[2] = {d0 * 2, d0 * d1 * 2};
    cuuint32_t box[3] = {64, 128, 1};
    cuuint32_t es[3] = {1, 1, 1};
    enc(m, CU_TENSOR_MAP_DATA_TYPE_BFLOAT16, 3, base, dims, strides, box, es,
        CU_TENSOR_MAP_INTERLEAVE_NONE, CU_TENSOR_MAP_SWIZZLE_128B,
        CU_TENSOR_MAP_L2_PROMOTION_L2_128B, CU_TENSOR_MAP_FLOAT_OOB_FILL_NONE);
}

// ---------------- launch ----------------------------------------------------
extern "C" void kernel_launch(void* const* d_in, const int* in_sizes, int n_in,
                              void* d_out, int out_size) {
    const float* x  = (const float*)d_in[0];
    const float* W1 = (const float*)d_in[2];
    const float* W2 = (const float*)d_in[3];
    const float* W3 = (const float*)d_in[4];
    const float* Wg = (const float*)d_in[5];
    const float* Wc = (const float*)d_in[6];
    const float* bc = (const float*)d_in[7];
    float* out = (float*)d_out;

    cudaFuncSetAttribute(ffn1_mma, cudaFuncAttributeMaxDynamicSharedMemorySize, FFN1_SMEM);
    cudaFuncSetAttribute(ffn2_mma, cudaFuncAttributeMaxDynamicSharedMemorySize, FFN2_SMEM);

    __nv_bfloat16 *xh, *xl, *w1h, *w1l, *w3h, *w3l, *w2h, *w2l;
    cudaGetSymbolAddress((void**)&xh,  g_xh);
    cudaGetSymbolAddress((void**)&xl,  g_xl);
    cudaGetSymbolAddress((void**)&w1h, g_w1h);
    cudaGetSymbolAddress((void**)&w1l, g_w1l);
    cudaGetSymbolAddress((void**)&w3h, g_w3h);
    cudaGetSymbolAddress((void**)&w3l, g_w3l);
    cudaGetSymbolAddress((void**)&w2h, g_w2h);
    cudaGetSymbolAddress((void**)&w2l, g_w2l);

    void* pfn = nullptr;
    cudaDriverEntryPointQueryResult qres;
    cudaGetDriverEntryPoint("cuTensorMapEncodeTiled", &pfn,
                            cudaEnableDefault, &qres);
    PFN_tme enc = (PFN_tme)pfn;
    CUtensorMap mW1h, mW1l, mW3h, mW3l, mW2h, mW2l;
    encode_w(enc, &mW1h, w1h, Dd, Hh, Ee);
    encode_w(enc, &mW1l, w1l, Dd, Hh, Ee);
    encode_w(enc, &mW3h, w3h, Dd, Hh, Ee);
    encode_w(enc, &mW3l, w3l, Dd, Hh, Ee);
    encode_w(enc, &mW2h, w2h, Hh, Dd, Ee);
    encode_w(enc, &mW2l, w2l, Hh, Dd, Ee);

    init_kernel<<<512, 256>>>(out);
    gating_kernel<<<Nn, 256>>>(x, Wg, out);
    scan_kernel<<<1, 1>>>();
    scatter_kernel<<<(Nn + 255) / 256, 256>>>();
    split_kernel<<<1024, 256>>>(x,  xh,  xl,  (size_t)Nn * Dd);
    split_kernel<<<2048, 256>>>(W1, w1h, w1l, (size_t)Ee * Hh * Dd);
    split_kernel<<<2048, 256>>>(W3, w3h, w3l, (size_t)Ee * Hh * Dd);
    split_kernel<<<2048, 256>>>(W2, w2h, w2l, (size_t)Ee * Dd * Hh);
    ffn1_mma<<<dim3(Nn / BM, Hh / BN, Ee), 256, FFN1_SMEM>>>(
        mW1h, mW1l, mW3h, mW3l, x, W1, W3);
    vproj_kernel<<<dim3(Hh / 256, Ee), 256>>>(W2, Wc);
    ffn2_mma<<<dim3(Nn / BM2, Dd / BN, Ee), 256, FFN2_SMEM>>>(mW2h, mW2l, W2, out);
    cls_kernel<<<Bb * 2, 256>>>();
    elog_kernel<<<1, 32>>>(bc, out);
}

// round 9
// speedup vs baseline: 1.0597x; 1.0597x over previous
#include <cuda_runtime.h>
#include <cuda.h>
#include <cuda_bf16.h>
#include <math.h>
#include <cstdint>

// arch guard: tcgen05 only exists on the sm_103a-specific compilation pass
#if !defined(__CUDA_ARCH__) || defined(__CUDA_ARCH_FEAT_SM103_ALL) || \
    (defined(__CUDA_ARCH_SPECIFIC__) && (__CUDA_ARCH_SPECIFIC__ == 1030))
#define USE_TCG 1
#else
#define USE_TCG 0
#endif

// Problem constants
#define Bb 4
#define Ss 1024
#define Dd 1024
#define Hh 2048
#define Ee 8
#define Nn (Bb*Ss)      // 4096 tokens
#define Rr (2*Nn)       // 8192 expert-rows (top-2)

// Output layout (concatenated float32)
#define OUT_FINAL 0
#define OUT_GATE  (Nn*Dd)
#define OUT_ELOG  (OUT_GATE + Nn*Ee)
#define OUT_ROUT  (OUT_ELOG + Ee*Bb)

// ---------------- device scratch ---------------------------------------
__device__ int   g_count[Ee];
__device__ int   g_offset[Ee];
__device__ int   g_cursor[Ee];
__device__ int   g_sel[Nn*2];
__device__ float g_selw[Nn*2];
__device__ int   g_row_token[Rr];
__device__ float g_row_weight[Rr];
__device__ int   g_slot_row[Nn*2];
__device__ float g_v[Ee*Hh];
__device__ float g_cls_delta[Ee*Bb];
// pre-split hi/lo bf16 operands
__device__ __nv_bfloat16 g_xh[(size_t)Nn*Dd];
__device__ __nv_bfloat16 g_xl[(size_t)Nn*Dd];
__device__ __nv_bfloat16 g_w1h[(size_t)Ee*Hh*Dd];
__device__ __nv_bfloat16 g_w1l[(size_t)Ee*Hh*Dd];
__device__ __nv_bfloat16 g_w3h[(size_t)Ee*Hh*Dd];
__device__ __nv_bfloat16 g_w3l[(size_t)Ee*Hh*Dd];
__device__ __nv_bfloat16 g_w2h[(size_t)Ee*Dd*Hh];
__device__ __nv_bfloat16 g_w2l[(size_t)Ee*Dd*Hh];
__device__ __nv_bfloat16 g_hh[(size_t)Rr*Hh];
__device__ __nv_bfloat16 g_hl[(size_t)Rr*Hh];

// ================= inline PTX helpers =====================================
__device__ __forceinline__ uint32_t smem_to_u32(const void* p) {
    uint32_t a;
    asm("{ .reg .u64 t; cvta.to.shared.u64 t, %1; cvt.u32.u64 %0, t; }"
        : "=r"(a) : "l"(p));
    return a;
}
#define CP16(dst, src) \
    asm volatile("cp.async.cg.shared.global [%0], [%1], 16;" \
                 :: "r"((uint32_t)(dst)), "l"(src) : "memory")
#define CP_COMMIT() asm volatile("cp.async.commit_group;" ::: "memory")
#define CP_WAIT0()  asm volatile("cp.async.wait_group 0;" ::: "memory")
#define TMA_LOAD_3D(smem_addr, tmap, cx, cy, cz, mbar) \
    asm volatile( \
        "cp.async.bulk.tensor.3d.shared::cta.global.tile.mbarrier::complete_tx::bytes " \
        "[%0], [%1, {%2, %3, %4}], [%5];" \
        :: "r"((uint32_t)(smem_addr)), "l"(tmap), "r"((int32_t)(cx)), \
           "r"((int32_t)(cy)), "r"((int32_t)(cz)), "r"((uint32_t)(mbar)) \
        : "memory")
#define MBAR_EXPECT_TX(mbar, bytes) \
    asm volatile("mbarrier.arrive.expect_tx.shared.b64 _, [%0], %1;" \
                 :: "r"((uint32_t)(mbar)), "r"((uint32_t)(bytes)) : "memory")

#if USE_TCG
__device__ __forceinline__ uint32_t elect_one_pred() {
    uint32_t pred;
    asm volatile("{\n\t.reg .pred p;\n\telect.sync _|p, 0xFFFFFFFF;\n\t"
                 "selp.b32 %0, 1, 0, p;\n\t}" : "=r"(pred));
    return pred;
}
#define TCG_ALLOC(smem_addr, n) \
    asm volatile("tcgen05.alloc.cta_group::1.sync.aligned.shared::cta.b32 [%0], %1;" \
                 :: "r"((uint32_t)(smem_addr)), "r"((uint32_t)(n)) : "memory")
#define TCG_DEALLOC(tmem, n) \
    asm volatile("tcgen05.dealloc.cta_group::1.sync.aligned.b32 %0, %1;" \
                 :: "r"(tmem), "r"((uint32_t)(n)))
#define TCG_RELINQ() \
    asm volatile("tcgen05.relinquish_alloc_permit.cta_group::1.sync.aligned;")
#define TCG_COMMIT(mbar) \
    asm volatile("tcgen05.commit.cta_group::1.mbarrier::arrive::one.shared::cluster.b64 [%0];" \
                 :: "r"((uint32_t)(mbar)) : "memory")
#define TCG_FENCE_AFTER() \
    asm volatile("tcgen05.fence::after_thread_sync;" ::: "memory")
#define TCG_WAIT_LD() \
    asm volatile("tcgen05.wait::ld.sync.aligned;" ::: "memory")
#define FENCE_ASYNC_SHARED() \
    asm volatile("fence.proxy.async.shared::cta;" ::: "memory")
#define MBAR_INIT(mbar, cnt) \
    asm volatile("mbarrier.init.shared.b64 [%0], %1;" \
                 :: "r"((uint32_t)(mbar)), "r"((uint32_t)(cnt)) : "memory")
#define MBAR_WAIT(mbar, parity) do { \
    uint32_t _m = (uint32_t)(mbar); uint32_t _p = (uint32_t)(parity); uint32_t _d; \
    asm volatile("{\n\t.reg .pred p;\n\t" \
        "mbarrier.try_wait.parity.acquire.cta.shared::cta.b64 p, [%1], %2;\n\t" \
        "selp.b32 %0, 1, 0, p;\n\t}" : "=r"(_d) : "r"(_m), "r"(_p) : "memory"); \
    if (!_d) { \
        asm volatile("{\n\t.reg .pred P1;\n\t" \
            "WL_%=:\n\t" \
            "mbarrier.try_wait.parity.acquire.cta.shared::cta.b64 P1, [%0], %1, 0x989680;\n\t" \
            "@P1 bra.uni WD_%=;\n\t" \
            "bra.uni WL_%=;\n\t" \
            "WD_%=:\n\t}" :: "r"(_m), "r"(_p) : "memory"); \
    } \
} while (0)
#define TCG_LD_X32(r, tm) \
    asm volatile("tcgen05.ld.sync.aligned.32x32b.x32.b32 " \
        "{%0, %1, %2, %3, %4, %5, %6, %7, %8, %9, %10, %11, %12, %13, %14, %15, " \
        " %16, %17, %18, %19, %20, %21, %22, %23, %24, %25, %26, %27, %28, %29, %30, %31}, [%32];" \
        : "=r"((r)[0]), "=r"((r)[1]), "=r"((r)[2]), "=r"((r)[3]), \
          "=r"((r)[4]), "=r"((r)[5]), "=r"((r)[6]), "=r"((r)[7]), \
          "=r"((r)[8]), "=r"((r)[9]), "=r"((r)[10]), "=r"((r)[11]), \
          "=r"((r)[12]), "=r"((r)[13]), "=r"((r)[14]), "=r"((r)[15]), \
          "=r"((r)[16]), "=r"((r)[17]), "=r"((r)[18]), "=r"((r)[19]), \
          "=r"((r)[20]), "=r"((r)[21]), "=r"((r)[22]), "=r"((r)[23]), \
          "=r"((r)[24]), "=r"((r)[25]), "=r"((r)[26]), "=r"((r)[27]), \
          "=r"((r)[28]), "=r"((r)[29]), "=r"((r)[30]), "=r"((r)[31]) \
        : "r"(tm))

__device__ __forceinline__ void mma_f16_ss(uint32_t d, uint64_t a, uint64_t b,
                                           uint32_t idesc, bool en) {
    uint32_t e = en ? 1u : 0u;
    asm volatile("{\n\t.reg .pred p;\n\tsetp.ne.u32 p, %5, 0;\n\t"
        "tcgen05.mma.cta_group::1.kind::f16 [%0], %1, %2, %3, {%4, %4, %4, %4}, p;\n\t}"
        :: "r"(d), "l"(a), "l"(b), "r"(idesc), "r"(0u), "r"(e) : "memory");
}

// SW128 smem descriptor: layout=2, version=1, SBO=64, LBO=1
static __device__ __forceinline__ uint64_t make_desc(uint32_t addr) {
    return ((uint64_t)2 << 61) | ((uint64_t)1 << 46) | ((uint64_t)64 << 32) |
           ((uint64_t)1 << 16) | ((uint64_t)(addr >> 4) & 0x3FFF);
}
#endif // USE_TCG

// idesc: dtype F32, a/b BF16, M=128 (8<<24), N=128 (16<<17)
#define IDESC_128x128 (0x490u | (16u << 17) | (8u << 24))

// GEMM tile constants
#define BM 128
#define BN 128
#define BK 64
#define BM2 256                       // ffn2 rows per CTA (two accumulators)
// SW128 tile offset for a 128x64 bf16 tile (single atom column)
__device__ __forceinline__ uint32_t tile_off(int r, int c) {
    uint32_t off = (uint32_t)((r >> 3) * 1024 + (r & 7) * 128 + c * 2);
    return off ^ ((off >> 3) & 0x70u);
}

// SMEM maps (single-buffered, occ 2)
#define T_SZ 16384
#define HDR1 1024                     // ffn1: tmem @0, mma mbar @8, tok @64
#define FFN1_SMEM (HDR1 + 6*T_SZ)     // 99328
#define HDR2 2048                     // ffn2: tmem @0, mma @8, tma @16, arow @64
#define FFN2_SMEM (HDR2 + 6*T_SZ)     // 100352  (<= 114688, occ 2)

// ---------------- init ----------------------------------------------------
__global__ void init_kernel(float* __restrict__ out) {
    size_t i = (size_t)blockIdx.x * blockDim.x + threadIdx.x;
    size_t stride = (size_t)gridDim.x * blockDim.x;
    for (size_t j = i; j < (size_t)Nn * Dd; j += stride)
        out[OUT_FINAL + j] = 0.0f;
    if (blockIdx.x == 0) {
        if (threadIdx.x < Ee) { g_count[threadIdx.x] = 0; g_cursor[threadIdx.x] = 0; }
        if (threadIdx.x < Ee * Bb) g_cls_delta[threadIdx.x] = 0.0f;
    }
}

// ---------------- fp32 -> bf16 hi/lo split --------------------------------
__global__ void split_kernel(const float* __restrict__ s,
                             __nv_bfloat16* __restrict__ hi,
                             __nv_bfloat16* __restrict__ lo, size_t n) {
    size_t i = ((size_t)blockIdx.x * blockDim.x + threadIdx.x) * 8;
    size_t stride = (size_t)gridDim.x * blockDim.x * 8;
    for (; i < n; i += stride) {
        float4 v0 = *(const float4*)(s + i);
        float4 v1 = *(const float4*)(s + i + 4);
        float f[8] = {v0.x, v0.y, v0.z, v0.w, v1.x, v1.y, v1.z, v1.w};
        uint16_t hb[8], lb[8];
        #pragma unroll
        for (int j = 0; j < 8; j++) {
            __nv_bfloat16 h = __float2bfloat16_rn(f[j]);
            __nv_bfloat16 l = __float2bfloat16_rn(f[j] - __bfloat162float(h));
            hb[j] = *(uint16_t*)&h;  lb[j] = *(uint16_t*)&l;
        }
        uint4 hv, lv;
        hv.x = ((uint32_t)hb[1] << 16) | hb[0];
        hv.y = ((uint32_t)hb[3] << 16) | hb[2];
        hv.z = ((uint32_t)hb[5] << 16) | hb[4];
        hv.w = ((uint32_t)hb[7] << 16) | hb[6];
        lv.x = ((uint32_t)lb[1] << 16) | lb[0];
        lv.y = ((uint32_t)lb[3] << 16) | lb[2];
        lv.z = ((uint32_t)lb[5] << 16) | lb[4];
        lv.w = ((uint32_t)lb[7] << 16) | lb[6];
        *(uint4*)(hi + i) = hv;
        *(uint4*)(lo + i) = lv;
    }
}

// ---------------- gating --------------------------------------------------
__global__ void gating_kernel(const float* __restrict__ x,
                              const float* __restrict__ Wg,
                              float* __restrict__ out) {
    int n = blockIdx.x;
    __shared__ float xs[Dd];
    __shared__ float logits[Ee];
    for (int i = threadIdx.x; i < Dd; i += blockDim.x)
        xs[i] = x[(size_t)n * Dd + i];
    __syncthreads();
    int warp = threadIdx.x >> 5, lane = threadIdx.x & 31;
    const float* w = Wg + warp * Dd;
    float s = 0.0f;
    for (int i = lane; i < Dd; i += 32) s += xs[i] * w[i];
    #pragma unroll
    for (int o = 16; o > 0; o >>= 1) s += __shfl_down_sync(0xffffffffu, s, o);
    if (lane == 0) logits[warp] = s;
    __syncthreads();
    if (threadIdx.x == 0) {
        float m = logits[0];
        #pragma unroll
        for (int e = 1; e < Ee; e++) m = fmaxf(m, logits[e]);
        float p[Ee]; float den = 0.0f;
        #pragma unroll
        for (int e = 0; e < Ee; e++) { p[e] = expf(logits[e] - m); den += p[e]; }
        float inv = 1.0f / den;
        #pragma unroll
        for (int e = 0; e < Ee; e++) {
            p[e] *= inv;
            out[OUT_GATE + n * Ee + e] = logits[e];
            out[OUT_ROUT + n * Ee + e] = p[e];
        }
        int i0 = 0;
        #pragma unroll
        for (int e = 1; e < Ee; e++) if (p[e] > p[i0]) i0 = e;
        int i1 = (i0 == 0) ? 1 : 0;
        #pragma unroll
        for (int e = 0; e < Ee; e++) if (e != i0 && p[e] > p[i1]) i1 = e;
        float sw = p[i0] + p[i1];
        g_sel[2*n] = i0;  g_sel[2*n+1] = i1;
        g_selw[2*n] = p[i0] / sw;  g_selw[2*n+1] = p[i1] / sw;
        atomicAdd(&g_count[i0], 1);
        atomicAdd(&g_count[i1], 1);
    }
}

__global__ void scan_kernel() {
    int o = 0;
    for (int e = 0; e < Ee; e++) { g_offset[e] = o; o += g_count[e]; }
}

__global__ void scatter_kernel() {
    int n = blockIdx.x * blockDim.x + threadIdx.x;
    if (n >= Nn) return;
    #pragma unroll
    for (int s = 0; s < 2; s++) {
        int e = g_sel[2*n + s];
        int pos = atomicAdd(&g_cursor[e], 1);
        int r = g_offset[e] + pos;
        g_row_token[r] = n;
        g_row_weight[r] = g_selw[2*n + s];
        g_slot_row[2*n + s] = r;
    }
}

// =================== FFN1 (unchanged from R6 best) =========================
__global__ __launch_bounds__(256, 2) void ffn1_mma(
    const float* __restrict__ x,
    const float* __restrict__ W1,
    const float* __restrict__ W3) {
    int e = blockIdx.z;
    int cnt = g_count[e];
    int row0 = blockIdx.x * BM;
    if (row0 >= cnt) return;
    int off = g_offset[e];
    int col0 = blockIdx.y * BN;

#if USE_TCG
    extern __shared__ __align__(1024) char smem[];
    uint32_t sb = smem_to_u32(smem);
    int tid = threadIdx.x, wid = tid >> 5, lid = tid & 31;

    int* tok = (int*)(smem + 64);
    if (tid < 128) tok[tid] = g_row_token[off + min(row0 + tid, cnt - 1)];
    if (wid == 0) TCG_ALLOC(sb + 0, 256);
    if (tid == 0) MBAR_INIT(sb + 8, 1);
    __syncthreads();
    uint32_t tmem;
    asm volatile("ld.shared.b32 %0, [%1];" : "=r"(tmem) : "r"(sb + 0));
    if (wid == 0) TCG_RELINQ();

    const uint64_t dAH  = make_desc(sb + HDR1);
    const uint64_t dAL  = make_desc(sb + HDR1 + T_SZ);
    const uint64_t dB1H = make_desc(sb + HDR1 + 2*T_SZ);
    const uint64_t dB1L = make_desc(sb + HDR1 + 3*T_SZ);
    const uint64_t dB3H = make_desc(sb + HDR1 + 4*T_SZ);
    const uint64_t dB3L = make_desc(sb + HDR1 + 5*T_SZ);

    int lr = tid >> 3;
    int lc = (tid & 7) << 3;

    const int KCH = Dd / BK;      // 16
    for (int c = 0; c < KCH; c++) {
        if (c > 0) MBAR_WAIT(sb + 8, (c - 1) & 1);
        int k0 = c * BK;
        #pragma unroll
        for (int p = 0; p < 4; p++) {
            int r = p * 32 + lr;
            uint32_t so = sb + HDR1 + tile_off(r, lc);
            size_t ax = (size_t)tok[r] * Dd + k0 + lc;
            size_t wx = ((size_t)e * Hh + col0 + r) * Dd + k0 + lc;
            CP16(so,          g_xh  + ax);
            CP16(so + T_SZ,   g_xl  + ax);
            CP16(so + 2*T_SZ, g_w1h + wx);
            CP16(so + 3*T_SZ, g_w1l + wx);
            CP16(so + 4*T_SZ, g_w3h + wx);
            CP16(so + 5*T_SZ, g_w3l + wx);
        }
        CP_COMMIT();
        CP_WAIT0();
        FENCE_ASYNC_SHARED();
        __syncthreads();
        if (wid == 0 && elect_one_pred()) {
            #pragma unroll
            for (int s = 0; s < 4; s++) {
                uint64_t o = (uint64_t)(s * 2);
                bool first = (c == 0) && (s == 0);
                mma_f16_ss(tmem + 0,   dAH + o, dB1H + o, IDESC_128x128, !first);
                mma_f16_ss(tmem + 0,   dAH + o, dB1L + o, IDESC_128x128, true);
                mma_f16_ss(tmem + 0,   dAL + o, dB1H + o, IDESC_128x128, true);
                mma_f16_ss(tmem + 128, dAH + o, dB3H + o, IDESC_128x128, !first);
                mma_f16_ss(tmem + 128, dAH + o, dB3L + o, IDESC_128x128, true);
                mma_f16_ss(tmem + 128, dAL + o, dB3H + o, IDESC_128x128, true);
            }
            TCG_COMMIT(sb + 8);
        }
    }
    MBAR_WAIT(sb + 8, (KCH - 1) & 1);
    TCG_FENCE_AFTER();

    {
        int sub = wid & 3;
        int colh = (wid >> 2) * 64;
        int gr = row0 + sub * 32 + lid;
        bool valid = gr < cnt;
        size_t hbase = (size_t)(off + gr) * Hh + col0;
        #pragma unroll
        for (int half = 0; half < 2; half++) {
            int cc = colh + half * 32;
            uint32_t r1[32], r3[32];
            TCG_LD_X32(r1, tmem + cc);
            TCG_LD_X32(r3, tmem + 128 + cc);
            TCG_WAIT_LD();
            if (valid) {
                #pragma unroll
                for (int j = 0; j < 32; j += 2) {
                    float z0 = __uint_as_float(r1[j]);
                    float z1 = __uint_as_float(r1[j + 1]);
                    float h0 = z0 * (1.0f/(1.0f+__expf(-z0))) * __uint_as_float(r3[j]);
                    float h1 = z1 * (1.0f/(1.0f+__expf(-z1))) * __uint_as_float(r3[j+1]);
                    __nv_bfloat16 h0h = __float2bfloat16_rn(h0);
                    __nv_bfloat16 h1h = __float2bfloat16_rn(h1);
                    __nv_bfloat16 h0l = __float2bfloat16_rn(h0 - __bfloat162float(h0h));
                    __nv_bfloat16 h1l = __float2bfloat16_rn(h1 - __bfloat162float(h1h));
                    uint32_t hp = ((uint32_t)*(uint16_t*)&h1h << 16) | *(uint16_t*)&h0h;
                    uint32_t lp = ((uint32_t)*(uint16_t*)&h1l << 16) | *(uint16_t*)&h0l;
                    *(uint32_t*)(g_hh + hbase + cc + j) = hp;
                    *(uint32_t*)(g_hl + hbase + cc + j) = lp;
                }
            }
        }
    }
    __syncthreads();
    if (wid == 0) TCG_DEALLOC(tmem, 256);
#else
    int tid = threadIdx.x;
    for (int idx = tid; idx < BM * BN; idx += 256) {
        int r = row0 + idx / BN;
        if (r >= cnt) continue;
        int cc = col0 + (idx % BN);
        int tokn = g_row_token[off + r];
        float a1 = 0.0f, a3 = 0.0f;
        for (int k = 0; k < Dd; k++) {
            float xv = x[(size_t)tokn * Dd + k];
            a1 += xv * W1[((size_t)e * Hh + cc) * Dd + k];
            a3 += xv * W3[((size_t)e * Hh + cc) * Dd + k];
        }
        float hv = a1 * (1.0f / (1.0f + __expf(-a1))) * a3;
        __nv_bfloat16 hh = __float2bfloat16_rn(hv);
        g_hh[(size_t)(off + r) * Hh + cc] = hh;
        g_hl[(size_t)(off + r) * Hh + cc] =
            __float2bfloat16_rn(hv - __bfloat162float(hh));
    }
#endif
}

// =================== FFN2: BM2=256, occ 2, single-buffer ===================
// Two M=128 accumulator sets share each W2 tile; W2 via TMA, h via cp.async.
__global__ __launch_bounds__(256, 2) void ffn2_mma(
    const __grid_constant__ CUtensorMap t_w2h,
    const __grid_constant__ CUtensorMap t_w2l,
    const float* __restrict__ W2, float* __restrict__ out) {
    int e = blockIdx.z;
    int cnt = g_count[e];
    int row0 = blockIdx.x * BM2;
    if (row0 >= cnt) return;
    int off = g_offset[e];
    int col0 = blockIdx.y * BN;

#if USE_TCG
    extern __shared__ __align__(1024) char smem[];
    uint32_t sb = smem_to_u32(smem);
    int tid = threadIdx.x, wid = tid >> 5, lid = tid & 31;

    int* arow = (int*)(smem + 64);
    arow[tid] = off + min(row0 + tid, cnt - 1);
    if (wid == 0) TCG_ALLOC(sb + 0, 256);
    if (tid == 0) { MBAR_INIT(sb + 8, 1); MBAR_INIT(sb + 16, 1); }
    __syncthreads();
    uint32_t tmem;
    asm volatile("ld.shared.b32 %0, [%1];" : "=r"(tmem) : "r"(sb + 0));
    if (wid == 0) TCG_RELINQ();

    const uint64_t dA0H = make_desc(sb + HDR2);
    const uint64_t dA0L = make_desc(sb + HDR2 + T_SZ);
    const uint64_t dA1H = make_desc(sb + HDR2 + 2*T_SZ);
    const uint64_t dA1L = make_desc(sb + HDR2 + 3*T_SZ);
    const uint64_t dBH  = make_desc(sb + HDR2 + 4*T_SZ);
    const uint64_t dBL  = make_desc(sb + HDR2 + 5*T_SZ);

    int lr = tid >> 3;
    int lc = (tid & 7) << 3;

    const int KCH = Hh / BK;      // 32
    for (int c = 0; c < KCH; c++) {
        if (c > 0) MBAR_WAIT(sb + 8, (c - 1) & 1);
        int k0 = c * BK;
        if (tid == 0) {
            MBAR_EXPECT_TX(sb + 16, 2 * T_SZ);
            TMA_LOAD_3D(sb + HDR2 + 4*T_SZ, &t_w2h, k0, col0, e, sb + 16);
            TMA_LOAD_3D(sb + HDR2 + 5*T_SZ, &t_w2l, k0, col0, e, sb + 16);
        }
        #pragma unroll
        for (int p = 0; p < 4; p++) {
            int r = p * 32 + lr;
            uint32_t so = sb + HDR2 + tile_off(r, lc);
            size_t a0 = (size_t)arow[r] * Hh + k0 + lc;
            size_t a1 = (size_t)arow[r + 128] * Hh + k0 + lc;
            CP16(so,          g_hh + a0);
            CP16(so + T_SZ,   g_hl + a0);
            CP16(so + 2*T_SZ, g_hh + a1);
            CP16(so + 3*T_SZ, g_hl + a1);
        }
        CP_COMMIT();
        CP_WAIT0();
        FENCE_ASYNC_SHARED();
        __syncthreads();
        if (wid == 0) {
            MBAR_WAIT(sb + 16, c & 1);
            if (elect_one_pred()) {
                #pragma unroll
                for (int s = 0; s < 4; s++) {
                    uint64_t o = (uint64_t)(s * 2);
                    bool first = (c == 0) && (s == 0);
                    mma_f16_ss(tmem + 0,   dA0H + o, dBH + o, IDESC_128x128, !first);
                    mma_f16_ss(tmem + 0,   dA0H + o, dBL + o, IDESC_128x128, true);
                    mma_f16_ss(tmem + 0,   dA0L + o, dBH + o, IDESC_128x128, true);
                    mma_f16_ss(tmem + 128, dA1H + o, dBH + o, IDESC_128x128, !first);
                    mma_f16_ss(tmem + 128, dA1H + o, dBL + o, IDESC_128x128, true);
                    mma_f16_ss(tmem + 128, dA1L + o, dBH + o, IDESC_128x128, true);
                }
                TCG_COMMIT(sb + 8);
            }
        }
    }
    MBAR_WAIT(sb + 8, (KCH - 1) & 1);
    TCG_FENCE_AFTER();

    {
        int mblk = wid >> 2;          // which 128-row accumulator
        int sub = wid & 3;
        int gr = row0 + mblk * 128 + sub * 32 + lid;
        bool valid = gr < cnt;
        int tokn = valid ? g_row_token[off + gr] : 0;
        float wgt = valid ? g_row_weight[off + gr] : 0.0f;
        float* op = out + OUT_FINAL + (size_t)tokn * Dd + col0;
        uint32_t tbase = tmem + mblk * 128;
        #pragma unroll
        for (int q = 0; q < 4; q++) {
            int cc = q * 32;
            uint32_t r0[32];
            TCG_LD_X32(r0, tbase + cc);
            TCG_WAIT_LD();
            if (valid) {
                #pragma unroll
                for (int j = 0; j < 32; j++)
                    atomicAdd(&op[cc + j], __uint_as_float(r0[j]) * wgt);
            }
        }
    }
    __syncthreads();
    if (wid == 0) TCG_DEALLOC(tmem, 256);
#else
    int tid = threadIdx.x;
    for (int idx = tid; idx < BM2 * BN; idx += 256) {
        int r = row0 + idx / BN;
        if (r >= cnt) continue;
        int cc = col0 + (idx % BN);
        int tokn = g_row_token[off + r];
        float wgt = g_row_weight[off + r];
        float acc = 0.0f;
        for (int k = 0; k < Hh; k++) {
            float hv = __bfloat162float(g_hh[(size_t)(off + r) * Hh + k]) +
                       __bfloat162float(g_hl[(size_t)(off + r) * Hh + k]);
            acc += hv * W2[((size_t)e * Dd + cc) * Hh + k];
        }
        atomicAdd(&out[OUT_FINAL + (size_t)tokn * Dd + cc], acc * wgt);
    }
#endif
}

// ---------------- v[e] = Wc @ W2[e] ---------------------------------------
__global__ void vproj_kernel(const float* __restrict__ W2,
                             const float* __restrict__ Wc) {
    int e = blockIdx.y;
    int hh = blockIdx.x * blockDim.x + threadIdx.x;
    if (hh >= Hh) return;
    const float* W2e = W2 + (size_t)e * Dd * Hh;
    float s = 0.0f;
    for (int d = 0; d < Dd; d++) s += Wc[d] * W2e[(size_t)d * Hh + hh];
    g_v[e * Hh + hh] = s;
}

// ---------------- CLS delta per (batch, slot) ------------------------------
__global__ void cls_kernel() {
    int b = blockIdx.x >> 1;
    int s = blockIdx.x & 1;
    int n = b * Ss;
    int e = g_sel[2*n + s];
    int r = g_slot_row[2*n + s];
    float w = g_selw[2*n + s];
    const __nv_bfloat16* hp = g_hh + (size_t)r * Hh;
    const __nv_bfloat16* lp = g_hl + (size_t)r * Hh;
    const float* vp = g_v + e * Hh;
    float acc = 0.0f;
    for (int i = threadIdx.x; i < Hh; i += blockDim.x)
        acc += (__bfloat162float(hp[i]) + __bfloat162float(lp[i])) * vp[i];
    __shared__ float red[8];
    int lane = threadIdx.x & 31, warp = threadIdx.x >> 5;
    #pragma unroll
    for (int o = 16; o > 0; o >>= 1) acc += __shfl_down_sync(0xffffffffu, acc, o);
    if (lane == 0) red[warp] = acc;
    __syncthreads();
    if (threadIdx.x == 0) {
        float t = 0.0f;
        for (int i = 0; i < (int)(blockDim.x >> 5); i++) t += red[i];
        g_cls_delta[e * Bb + b] = w * t;
    }
}

__global__ void elog_kernel(const float* __restrict__ bc, float* __restrict__ out) {
    int b = threadIdx.x;
    if (b < Bb) {
        float cum = bc[0];
        for (int e = 0; e < Ee; e++) {
            cum += g_cls_delta[e * Bb + b];
            out[OUT_ELOG + e * Bb + b] = cum;
        }
    }
}

// ---------------- host: tensormap encode via driver entry point ------------
typedef CUresult (CUDAAPI *PFN_tme)(
    CUtensorMap*, CUtensorMapDataType, cuuint32_t, void*,
    const cuuint64_t*, const cuuint64_t*, const cuuint32_t*, const cuuint32_t*,
    CUtensorMapInterleave, CUtensorMapSwizzle, CUtensorMapL2promotion,
    CUtensorMapFloatOOBfill);

static void encode_w(PFN_tme enc, CUtensorMap* m, void* base,
                     uint64_t d0, uint64_t d1, uint64_t d2) {
    cuuint64_t dims[3] = {d0, d1, d2};
    cuuint64_t strides[2] = {d0 * 2, d0 * d1 * 2};
    cuuint32_t box[3] = {64, 128, 1};
    cuuint32_t es[3] = {1, 1, 1};
    enc(m, CU_TENSOR_MAP_DATA_TYPE_BFLOAT16, 3, base, dims, strides, box, es,
        CU_TENSOR_MAP_INTERLEAVE_NONE, CU_TENSOR_MAP_SWIZZLE_128B,
        CU_TENSOR_MAP_L2_PROMOTION_L2_128B, CU_TENSOR_MAP_FLOAT_OOB_FILL_NONE);
}

// ---------------- launch ----------------------------------------------------
extern "C" void kernel_launch(void* const* d_in, const int* in_sizes, int n_in,
                              void* d_out, int out_size) {
    const float* x  = (const float*)d_in[0];
    const float* W1 = (const float*)d_in[2];
    const float* W2 = (const float*)d_in[3];
    const float* W3 = (const float*)d_in[4];
    const float* Wg = (const float*)d_in[5];
    const float* Wc = (const float*)d_in[6];
    const float* bc = (const float*)d_in[7];
    float* out = (float*)d_out;

    cudaFuncSetAttribute(ffn1_mma, cudaFuncAttributeMaxDynamicSharedMemorySize, FFN1_SMEM);
    cudaFuncSetAttribute(ffn2_mma, cudaFuncAttributeMaxDynamicSharedMemorySize, FFN2_SMEM);

    __nv_bfloat16 *xh, *xl, *w1h, *w1l, *w3h, *w3l, *w2h, *w2l;
    cudaGetSymbolAddress((void**)&xh,  g_xh);
    cudaGetSymbolAddress((void**)&xl,  g_xl);
    cudaGetSymbolAddress((void**)&w1h, g_w1h);
    cudaGetSymbolAddress((void**)&w1l, g_w1l);
    cudaGetSymbolAddress((void**)&w3h, g_w3h);
    cudaGetSymbolAddress((void**)&w3l, g_w3l);
    cudaGetSymbolAddress((void**)&w2h, g_w2h);
    cudaGetSymbolAddress((void**)&w2l, g_w2l);

    void* pfn = nullptr;
    cudaDriverEntryPointQueryResult qres;
    cudaGetDriverEntryPoint("cuTensorMapEncodeTiled", &pfn,
                            cudaEnableDefault, &qres);
    PFN_tme enc = (PFN_tme)pfn;
    CUtensorMap mW2h, mW2l;
    encode_w(enc, &mW2h, w2h, Hh, Dd, Ee);
    encode_w(enc, &mW2l, w2l, Hh, Dd, Ee);

    init_kernel<<<512, 256>>>(out);
    gating_kernel<<<Nn, 256>>>(x, Wg, out);
    scan_kernel<<<1, 1>>>();
    scatter_kernel<<<(Nn + 255) / 256, 256>>>();
    split_kernel<<<1024, 256>>>(x,  xh,  xl,  (size_t)Nn * Dd);
    split_kernel<<<2048, 256>>>(W1, w1h, w1l, (size_t)Ee * Hh * Dd);
    split_kernel<<<2048, 256>>>(W3, w3h, w3l, (size_t)Ee * Hh * Dd);
    split_kernel<<<2048, 256>>>(W2, w2h, w2l, (size_t)Ee * Dd * Hh);
    ffn1_mma<<<dim3(Nn / BM, Hh / BN, Ee), 256, FFN1_SMEM>>>(x, W1, W3);
    vproj_kernel<<<dim3(Hh / 256, Ee), 256>>>(W2, Wc);
    ffn2_mma<<<dim3(Nn / BM2, Dd / BN, Ee), 256, FFN2_SMEM>>>(mW2h, mW2l, W2, out);
    cls_kernel<<<Bb * 2, 256>>>();
    elog_kernel<<<1, 32>>>(bc, out);
}

// round 10
// speedup vs baseline: 1.1679x; 1.1021x over previous
#include <cuda_runtime.h>
#include <cuda.h>
#include <cuda_bf16.h>
#include <math.h>
#include <cstdint>

// arch guard: tcgen05 only exists on the sm_103a-specific compilation pass
#if !defined(__CUDA_ARCH__) || defined(__CUDA_ARCH_FEAT_SM103_ALL) || \
    (defined(__CUDA_ARCH_SPECIFIC__) && (__CUDA_ARCH_SPECIFIC__ == 1030))
#define USE_TCG 1
#else
#define USE_TCG 0
#endif

// Problem constants
#define Bb 4
#define Ss 1024
#define Dd 1024
#define Hh 2048
#define Ee 8
#define Nn (Bb*Ss)      // 4096 tokens
#define Rr (2*Nn)       // 8192 expert-rows (top-2)

// Output layout (concatenated float32)
#define OUT_FINAL 0
#define OUT_GATE  (Nn*Dd)
#define OUT_ELOG  (OUT_GATE + Nn*Ee)
#define OUT_ROUT  (OUT_ELOG + Ee*Bb)

// ---------------- device scratch ---------------------------------------
__device__ int   g_count[Ee];
__device__ int   g_offset[Ee];
__device__ int   g_cursor[Ee];
__device__ int   g_sel[Nn*2];
__device__ float g_selw[Nn*2];
__device__ int   g_row_token[Rr];
__device__ float g_row_weight[Rr];
__device__ int   g_row_slot[Rr];
__device__ int   g_slot_row[Nn*2];
__device__ float g_v[Ee*Hh];
__device__ float g_cls_delta[Ee*Bb];
__device__ float g_part[2][(size_t)Nn*Dd];             // 32 MB partial sums
// pre-split hi/lo bf16 operands
__device__ __nv_bfloat16 g_xh[(size_t)Nn*Dd];
__device__ __nv_bfloat16 g_xl[(size_t)Nn*Dd];
__device__ __nv_bfloat16 g_w1h[(size_t)Ee*Hh*Dd];
__device__ __nv_bfloat16 g_w1l[(size_t)Ee*Hh*Dd];
__device__ __nv_bfloat16 g_w3h[(size_t)Ee*Hh*Dd];
__device__ __nv_bfloat16 g_w3l[(size_t)Ee*Hh*Dd];
__device__ __nv_bfloat16 g_w2h[(size_t)Ee*Dd*Hh];
__device__ __nv_bfloat16 g_w2l[(size_t)Ee*Dd*Hh];
__device__ __nv_bfloat16 g_hh[(size_t)Rr*Hh];
__device__ __nv_bfloat16 g_hl[(size_t)Rr*Hh];

// ================= inline PTX helpers =====================================
__device__ __forceinline__ uint32_t smem_to_u32(const void* p) {
    uint32_t a;
    asm("{ .reg .u64 t; cvta.to.shared.u64 t, %1; cvt.u32.u64 %0, t; }"
        : "=r"(a) : "l"(p));
    return a;
}
#define CP16(dst, src) \
    asm volatile("cp.async.cg.shared.global [%0], [%1], 16;" \
                 :: "r"((uint32_t)(dst)), "l"(src) : "memory")
#define CP_COMMIT() asm volatile("cp.async.commit_group;" ::: "memory")
#define CP_WAIT0()  asm volatile("cp.async.wait_group 0;" ::: "memory")
#define TMA_LOAD_3D(smem_addr, tmap, cx, cy, cz, mbar) \
    asm volatile( \
        "cp.async.bulk.tensor.3d.shared::cta.global.tile.mbarrier::complete_tx::bytes " \
        "[%0], [%1, {%2, %3, %4}], [%5];" \
        :: "r"((uint32_t)(smem_addr)), "l"(tmap), "r"((int32_t)(cx)), \
           "r"((int32_t)(cy)), "r"((int32_t)(cz)), "r"((uint32_t)(mbar)) \
        : "memory")
#define MBAR_EXPECT_TX(mbar, bytes) \
    asm volatile("mbarrier.arrive.expect_tx.shared.b64 _, [%0], %1;" \
                 :: "r"((uint32_t)(mbar)), "r"((uint32_t)(bytes)) : "memory")

#if USE_TCG
__device__ __forceinline__ uint32_t elect_one_pred() {
    uint32_t pred;
    asm volatile("{\n\t.reg .pred p;\n\telect.sync _|p, 0xFFFFFFFF;\n\t"
                 "selp.b32 %0, 1, 0, p;\n\t}" : "=r"(pred));
    return pred;
}
#define TCG_ALLOC(smem_addr, n) \
    asm volatile("tcgen05.alloc.cta_group::1.sync.aligned.shared::cta.b32 [%0], %1;" \
                 :: "r"((uint32_t)(smem_addr)), "r"((uint32_t)(n)) : "memory")
#define TCG_DEALLOC(tmem, n) \
    asm volatile("tcgen05.dealloc.cta_group::1.sync.aligned.b32 %0, %1;" \
                 :: "r"(tmem), "r"((uint32_t)(n)))
#define TCG_RELINQ() \
    asm volatile("tcgen05.relinquish_alloc_permit.cta_group::1.sync.aligned;")
#define TCG_COMMIT(mbar) \
    asm volatile("tcgen05.commit.cta_group::1.mbarrier::arrive::one.shared::cluster.b64 [%0];" \
                 :: "r"((uint32_t)(mbar)) : "memory")
#define TCG_FENCE_AFTER() \
    asm volatile("tcgen05.fence::after_thread_sync;" ::: "memory")
#define TCG_WAIT_LD() \
    asm volatile("tcgen05.wait::ld.sync.aligned;" ::: "memory")
#define FENCE_ASYNC_SHARED() \
    asm volatile("fence.proxy.async.shared::cta;" ::: "memory")
#define MBAR_INIT(mbar, cnt) \
    asm volatile("mbarrier.init.shared.b64 [%0], %1;" \
                 :: "r"((uint32_t)(mbar)), "r"((uint32_t)(cnt)) : "memory")
#define MBAR_WAIT(mbar, parity) do { \
    uint32_t _m = (uint32_t)(mbar); uint32_t _p = (uint32_t)(parity); uint32_t _d; \
    asm volatile("{\n\t.reg .pred p;\n\t" \
        "mbarrier.try_wait.parity.acquire.cta.shared::cta.b64 p, [%1], %2;\n\t" \
        "selp.b32 %0, 1, 0, p;\n\t}" : "=r"(_d) : "r"(_m), "r"(_p) : "memory"); \
    if (!_d) { \
        asm volatile("{\n\t.reg .pred P1;\n\t" \
            "WL_%=:\n\t" \
            "mbarrier.try_wait.parity.acquire.cta.shared::cta.b64 P1, [%0], %1, 0x989680;\n\t" \
            "@P1 bra.uni WD_%=;\n\t" \
            "bra.uni WL_%=;\n\t" \
            "WD_%=:\n\t}" :: "r"(_m), "r"(_p) : "memory"); \
    } \
} while (0)
#define TCG_LD_X32(r, tm) \
    asm volatile("tcgen05.ld.sync.aligned.32x32b.x32.b32 " \
        "{%0, %1, %2, %3, %4, %5, %6, %7, %8, %9, %10, %11, %12, %13, %14, %15, " \
        " %16, %17, %18, %19, %20, %21, %22, %23, %24, %25, %26, %27, %28, %29, %30, %31}, [%32];" \
        : "=r"((r)[0]), "=r"((r)[1]), "=r"((r)[2]), "=r"((r)[3]), \
          "=r"((r)[4]), "=r"((r)[5]), "=r"((r)[6]), "=r"((r)[7]), \
          "=r"((r)[8]), "=r"((r)[9]), "=r"((r)[10]), "=r"((r)[11]), \
          "=r"((r)[12]), "=r"((r)[13]), "=r"((r)[14]), "=r"((r)[15]), \
          "=r"((r)[16]), "=r"((r)[17]), "=r"((r)[18]), "=r"((r)[19]), \
          "=r"((r)[20]), "=r"((r)[21]), "=r"((r)[22]), "=r"((r)[23]), \
          "=r"((r)[24]), "=r"((r)[25]), "=r"((r)[26]), "=r"((r)[27]), \
          "=r"((r)[28]), "=r"((r)[29]), "=r"((r)[30]), "=r"((r)[31]) \
        : "r"(tm))

__device__ __forceinline__ void mma_f16_ss(uint32_t d, uint64_t a, uint64_t b,
                                           uint32_t idesc, bool en) {
    uint32_t e = en ? 1u : 0u;
    asm volatile("{\n\t.reg .pred p;\n\tsetp.ne.u32 p, %5, 0;\n\t"
        "tcgen05.mma.cta_group::1.kind::f16 [%0], %1, %2, %3, {%4, %4, %4, %4}, p;\n\t}"
        :: "r"(d), "l"(a), "l"(b), "r"(idesc), "r"(0u), "r"(e) : "memory");
}

// SW128 smem descriptor: layout=2, version=1, SBO=64, LBO=1
static __device__ __forceinline__ uint64_t make_desc(uint32_t addr) {
    return ((uint64_t)2 << 61) | ((uint64_t)1 << 46) | ((uint64_t)64 << 32) |
           ((uint64_t)1 << 16) | ((uint64_t)(addr >> 4) & 0x3FFF);
}
#endif // USE_TCG

// idesc: dtype F32, a/b BF16, M=128 (8<<24), N=128 (16<<17)
#define IDESC_128x128 (0x490u | (16u << 17) | (8u << 24))

// GEMM tile constants
#define BM 128
#define BN 128
#define BK 64
#define BM2 256                       // ffn2 rows per CTA (two accumulators)
// SW128 tile offset for a 128x64 bf16 tile (single atom column)
__device__ __forceinline__ uint32_t tile_off(int r, int c) {
    uint32_t off = (uint32_t)((r >> 3) * 1024 + (r & 7) * 128 + c * 2);
    return off ^ ((off >> 3) & 0x70u);
}

// SMEM maps (single-buffered, occ 2)
#define T_SZ 16384
#define HDR1 1024                     // ffn1: tmem @0, mma mbar @8, tok @64
#define FFN1_SMEM (HDR1 + 6*T_SZ)     // 99328
#define HDR2 2048                     // ffn2: tmem @0, mma @8, tma @16, arow @64
#define FFN2_SMEM (HDR2 + 6*T_SZ)     // 100352

// ---------------- init: counters only (no output zeroing) ------------------
__global__ void init_kernel() {
    if (threadIdx.x < Ee) { g_count[threadIdx.x] = 0; g_cursor[threadIdx.x] = 0; }
    if (threadIdx.x < Ee * Bb) g_cls_delta[threadIdx.x] = 0.0f;
}

// ---------------- fp32 -> bf16 hi/lo split --------------------------------
__global__ void split_kernel(const float* __restrict__ s,
                             __nv_bfloat16* __restrict__ hi,
                             __nv_bfloat16* __restrict__ lo, size_t n) {
    size_t i = ((size_t)blockIdx.x * blockDim.x + threadIdx.x) * 8;
    size_t stride = (size_t)gridDim.x * blockDim.x * 8;
    for (; i < n; i += stride) {
        float4 v0 = *(const float4*)(s + i);
        float4 v1 = *(const float4*)(s + i + 4);
        float f[8] = {v0.x, v0.y, v0.z, v0.w, v1.x, v1.y, v1.z, v1.w};
        uint16_t hb[8], lb[8];
        #pragma unroll
        for (int j = 0; j < 8; j++) {
            __nv_bfloat16 h = __float2bfloat16_rn(f[j]);
            __nv_bfloat16 l = __float2bfloat16_rn(f[j] - __bfloat162float(h));
            hb[j] = *(uint16_t*)&h;  lb[j] = *(uint16_t*)&l;
        }
        uint4 hv, lv;
        hv.x = ((uint32_t)hb[1] << 16) | hb[0];
        hv.y = ((uint32_t)hb[3] << 16) | hb[2];
        hv.z = ((uint32_t)hb[5] << 16) | hb[4];
        hv.w = ((uint32_t)hb[7] << 16) | hb[6];
        lv.x = ((uint32_t)lb[1] << 16) | lb[0];
        lv.y = ((uint32_t)lb[3] << 16) | lb[2];
        lv.z = ((uint32_t)lb[5] << 16) | lb[4];
        lv.w = ((uint32_t)lb[7] << 16) | lb[6];
        *(uint4*)(hi + i) = hv;
        *(uint4*)(lo + i) = lv;
    }
}

// ---------------- gating --------------------------------------------------
__global__ void gating_kernel(const float* __restrict__ x,
                              const float* __restrict__ Wg,
                              float* __restrict__ out) {
    int n = blockIdx.x;
    __shared__ float xs[Dd];
    __shared__ float logits[Ee];
    for (int i = threadIdx.x; i < Dd; i += blockDim.x)
        xs[i] = x[(size_t)n * Dd + i];
    __syncthreads();
    int warp = threadIdx.x >> 5, lane = threadIdx.x & 31;
    const float* w = Wg + warp * Dd;
    float s = 0.0f;
    for (int i = lane; i < Dd; i += 32) s += xs[i] * w[i];
    #pragma unroll
    for (int o = 16; o > 0; o >>= 1) s += __shfl_down_sync(0xffffffffu, s, o);
    if (lane == 0) logits[warp] = s;
    __syncthreads();
    if (threadIdx.x == 0) {
        float m = logits[0];
        #pragma unroll
        for (int e = 1; e < Ee; e++) m = fmaxf(m, logits[e]);
        float p[Ee]; float den = 0.0f;
        #pragma unroll
        for (int e = 0; e < Ee; e++) { p[e] = expf(logits[e] - m); den += p[e]; }
        float inv = 1.0f / den;
        #pragma unroll
        for (int e = 0; e < Ee; e++) {
            p[e] *= inv;
            out[OUT_GATE + n * Ee + e] = logits[e];
            out[OUT_ROUT + n * Ee + e] = p[e];
        }
        int i0 = 0;
        #pragma unroll
        for (int e = 1; e < Ee; e++) if (p[e] > p[i0]) i0 = e;
        int i1 = (i0 == 0) ? 1 : 0;
        #pragma unroll
        for (int e = 0; e < Ee; e++) if (e != i0 && p[e] > p[i1]) i1 = e;
        float sw = p[i0] + p[i1];
        g_sel[2*n] = i0;  g_sel[2*n+1] = i1;
        g_selw[2*n] = p[i0] / sw;  g_selw[2*n+1] = p[i1] / sw;
        atomicAdd(&g_count[i0], 1);
        atomicAdd(&g_count[i1], 1);
    }
}

__global__ void scan_kernel() {
    int o = 0;
    for (int e = 0; e < Ee; e++) { g_offset[e] = o; o += g_count[e]; }
}

__global__ void scatter_kernel() {
    int n = blockIdx.x * blockDim.x + threadIdx.x;
    if (n >= Nn) return;
    #pragma unroll
    for (int s = 0; s < 2; s++) {
        int e = g_sel[2*n + s];
        int pos = atomicAdd(&g_cursor[e], 1);
        int r = g_offset[e] + pos;
        g_row_token[r] = n;
        g_row_weight[r] = g_selw[2*n + s];
        g_row_slot[r] = s;
        g_slot_row[2*n + s] = r;
    }
}

// =================== FFN1 (R6/R9 proven structure) =========================
__global__ __launch_bounds__(256, 2) void ffn1_mma(
    const float* __restrict__ x,
    const float* __restrict__ W1,
    const float* __restrict__ W3) {
    int e = blockIdx.z;
    int cnt = g_count[e];
    int row0 = blockIdx.x * BM;
    if (row0 >= cnt) return;
    int off = g_offset[e];
    int col0 = blockIdx.y * BN;

#if USE_TCG
    extern __shared__ __align__(1024) char smem[];
    uint32_t sb = smem_to_u32(smem);
    int tid = threadIdx.x, wid = tid >> 5, lid = tid & 31;

    int* tok = (int*)(smem + 64);
    if (tid < 128) tok[tid] = g_row_token[off + min(row0 + tid, cnt - 1)];
    if (wid == 0) TCG_ALLOC(sb + 0, 256);
    if (tid == 0) MBAR_INIT(sb + 8, 1);
    __syncthreads();
    uint32_t tmem;
    asm volatile("ld.shared.b32 %0, [%1];" : "=r"(tmem) : "r"(sb + 0));
    if (wid == 0) TCG_RELINQ();

    const uint64_t dAH  = make_desc(sb + HDR1);
    const uint64_t dAL  = make_desc(sb + HDR1 + T_SZ);
    const uint64_t dB1H = make_desc(sb + HDR1 + 2*T_SZ);
    const uint64_t dB1L = make_desc(sb + HDR1 + 3*T_SZ);
    const uint64_t dB3H = make_desc(sb + HDR1 + 4*T_SZ);
    const uint64_t dB3L = make_desc(sb + HDR1 + 5*T_SZ);

    int lr = tid >> 3;
    int lc = (tid & 7) << 3;

    const int KCH = Dd / BK;      // 16
    for (int c = 0; c < KCH; c++) {
        if (c > 0) MBAR_WAIT(sb + 8, (c - 1) & 1);
        int k0 = c * BK;
        #pragma unroll
        for (int p = 0; p < 4; p++) {
            int r = p * 32 + lr;
            uint32_t so = sb + HDR1 + tile_off(r, lc);
            size_t ax = (size_t)tok[r] * Dd + k0 + lc;
            size_t wx = ((size_t)e * Hh + col0 + r) * Dd + k0 + lc;
            CP16(so,          g_xh  + ax);
            CP16(so + T_SZ,   g_xl  + ax);
            CP16(so + 2*T_SZ, g_w1h + wx);
            CP16(so + 3*T_SZ, g_w1l + wx);
            CP16(so + 4*T_SZ, g_w3h + wx);
            CP16(so + 5*T_SZ, g_w3l + wx);
        }
        CP_COMMIT();
        CP_WAIT0();
        FENCE_ASYNC_SHARED();
        __syncthreads();
        if (wid == 0 && elect_one_pred()) {
            #pragma unroll
            for (int s = 0; s < 4; s++) {
                uint64_t o = (uint64_t)(s * 2);
                bool first = (c == 0) && (s == 0);
                mma_f16_ss(tmem + 0,   dAH + o, dB1H + o, IDESC_128x128, !first);
                mma_f16_ss(tmem + 0,   dAH + o, dB1L + o, IDESC_128x128, true);
                mma_f16_ss(tmem + 0,   dAL + o, dB1H + o, IDESC_128x128, true);
                mma_f16_ss(tmem + 128, dAH + o, dB3H + o, IDESC_128x128, !first);
                mma_f16_ss(tmem + 128, dAH + o, dB3L + o, IDESC_128x128, true);
                mma_f16_ss(tmem + 128, dAL + o, dB3H + o, IDESC_128x128, true);
            }
            TCG_COMMIT(sb + 8);
        }
    }
    MBAR_WAIT(sb + 8, (KCH - 1) & 1);
    TCG_FENCE_AFTER();

    {
        int sub = wid & 3;
        int colh = (wid >> 2) * 64;
        int gr = row0 + sub * 32 + lid;
        bool valid = gr < cnt;
        size_t hbase = (size_t)(off + gr) * Hh + col0;
        #pragma unroll
        for (int half = 0; half < 2; half++) {
            int cc = colh + half * 32;
            uint32_t r1[32], r3[32];
            TCG_LD_X32(r1, tmem + cc);
            TCG_LD_X32(r3, tmem + 128 + cc);
            TCG_WAIT_LD();
            if (valid) {
                #pragma unroll
                for (int j = 0; j < 32; j += 2) {
                    float z0 = __uint_as_float(r1[j]);
                    float z1 = __uint_as_float(r1[j + 1]);
                    float h0 = z0 * (1.0f/(1.0f+__expf(-z0))) * __uint_as_float(r3[j]);
                    float h1 = z1 * (1.0f/(1.0f+__expf(-z1))) * __uint_as_float(r3[j+1]);
                    __nv_bfloat16 h0h = __float2bfloat16_rn(h0);
                    __nv_bfloat16 h1h = __float2bfloat16_rn(h1);
                    __nv_bfloat16 h0l = __float2bfloat16_rn(h0 - __bfloat162float(h0h));
                    __nv_bfloat16 h1l = __float2bfloat16_rn(h1 - __bfloat162float(h1h));
                    uint32_t hp = ((uint32_t)*(uint16_t*)&h1h << 16) | *(uint16_t*)&h0h;
                    uint32_t lp = ((uint32_t)*(uint16_t*)&h1l << 16) | *(uint16_t*)&h0l;
                    *(uint32_t*)(g_hh + hbase + cc + j) = hp;
                    *(uint32_t*)(g_hl + hbase + cc + j) = lp;
                }
            }
        }
    }
    __syncthreads();
    if (wid == 0) TCG_DEALLOC(tmem, 256);
#else
    int tid = threadIdx.x;
    for (int idx = tid; idx < BM * BN; idx += 256) {
        int r = row0 + idx / BN;
        if (r >= cnt) continue;
        int cc = col0 + (idx % BN);
        int tokn = g_row_token[off + r];
        float a1 = 0.0f, a3 = 0.0f;
        for (int k = 0; k < Dd; k++) {
            float xv = x[(size_t)tokn * Dd + k];
            a1 += xv * W1[((size_t)e * Hh + cc) * Dd + k];
            a3 += xv * W3[((size_t)e * Hh + cc) * Dd + k];
        }
        float hv = a1 * (1.0f / (1.0f + __expf(-a1))) * a3;
        __nv_bfloat16 hh = __float2bfloat16_rn(hv);
        g_hh[(size_t)(off + r) * Hh + cc] = hh;
        g_hl[(size_t)(off + r) * Hh + cc] =
            __float2bfloat16_rn(hv - __bfloat162float(hh));
    }
#endif
}

// =================== FFN2: BM2=256, plain-store epilogue ===================
__global__ __launch_bounds__(256, 2) void ffn2_mma(
    const __grid_constant__ CUtensorMap t_w2h,
    const __grid_constant__ CUtensorMap t_w2l,
    const float* __restrict__ W2) {
    int e = blockIdx.z;
    int cnt = g_count[e];
    int row0 = blockIdx.x * BM2;
    if (row0 >= cnt) return;
    int off = g_offset[e];
    int col0 = blockIdx.y * BN;

#if USE_TCG
    extern __shared__ __align__(1024) char smem[];
    uint32_t sb = smem_to_u32(smem);
    int tid = threadIdx.x, wid = tid >> 5, lid = tid & 31;

    int* arow = (int*)(smem + 64);
    arow[tid] = off + min(row0 + tid, cnt - 1);
    if (wid == 0) TCG_ALLOC(sb + 0, 256);
    if (tid == 0) { MBAR_INIT(sb + 8, 1); MBAR_INIT(sb + 16, 1); }
    __syncthreads();
    uint32_t tmem;
    asm volatile("ld.shared.b32 %0, [%1];" : "=r"(tmem) : "r"(sb + 0));
    if (wid == 0) TCG_RELINQ();

    const uint64_t dA0H = make_desc(sb + HDR2);
    const uint64_t dA0L = make_desc(sb + HDR2 + T_SZ);
    const uint64_t dA1H = make_desc(sb + HDR2 + 2*T_SZ);
    const uint64_t dA1L = make_desc(sb + HDR2 + 3*T_SZ);
    const uint64_t dBH  = make_desc(sb + HDR2 + 4*T_SZ);
    const uint64_t dBL  = make_desc(sb + HDR2 + 5*T_SZ);

    int lr = tid >> 3;
    int lc = (tid & 7) << 3;

    const int KCH = Hh / BK;      // 32
    for (int c = 0; c < KCH; c++) {
        if (c > 0) MBAR_WAIT(sb + 8, (c - 1) & 1);
        int k0 = c * BK;
        if (tid == 0) {
            MBAR_EXPECT_TX(sb + 16, 2 * T_SZ);
            TMA_LOAD_3D(sb + HDR2 + 4*T_SZ, &t_w2h, k0, col0, e, sb + 16);
            TMA_LOAD_3D(sb + HDR2 + 5*T_SZ, &t_w2l, k0, col0, e, sb + 16);
        }
        #pragma unroll
        for (int p = 0; p < 4; p++) {
            int r = p * 32 + lr;
            uint32_t so = sb + HDR2 + tile_off(r, lc);
            size_t a0 = (size_t)arow[r] * Hh + k0 + lc;
            size_t a1 = (size_t)arow[r + 128] * Hh + k0 + lc;
            CP16(so,          g_hh + a0);
            CP16(so + T_SZ,   g_hl + a0);
            CP16(so + 2*T_SZ, g_hh + a1);
            CP16(so + 3*T_SZ, g_hl + a1);
        }
        CP_COMMIT();
        CP_WAIT0();
        FENCE_ASYNC_SHARED();
        __syncthreads();
        if (wid == 0) {
            MBAR_WAIT(sb + 16, c & 1);
            if (elect_one_pred()) {
                #pragma unroll
                for (int s = 0; s < 4; s++) {
                    uint64_t o = (uint64_t)(s * 2);
                    bool first = (c == 0) && (s == 0);
                    mma_f16_ss(tmem + 0,   dA0H + o, dBH + o, IDESC_128x128, !first);
                    mma_f16_ss(tmem + 0,   dA0H + o, dBL + o, IDESC_128x128, true);
                    mma_f16_ss(tmem + 0,   dA0L + o, dBH + o, IDESC_128x128, true);
                    mma_f16_ss(tmem + 128, dA1H + o, dBH + o, IDESC_128x128, !first);
                    mma_f16_ss(tmem + 128, dA1H + o, dBL + o, IDESC_128x128, true);
                    mma_f16_ss(tmem + 128, dA1L + o, dBH + o, IDESC_128x128, true);
                }
                TCG_COMMIT(sb + 8);
            }
        }
    }
    MBAR_WAIT(sb + 8, (KCH - 1) & 1);
    TCG_FENCE_AFTER();

    // plain-store epilogue into per-slot partial buffers
    {
        int mblk = wid >> 2;
        int sub = wid & 3;
        int gr = row0 + mblk * 128 + sub * 32 + lid;
        bool valid = gr < cnt;
        int tokn = valid ? g_row_token[off + gr] : 0;
        int slot = valid ? g_row_slot[off + gr] : 0;
        float wgt = valid ? g_row_weight[off + gr] : 0.0f;
        float* op = &g_part[slot][(size_t)tokn * Dd + col0];
        uint32_t tbase = tmem + mblk * 128;
        #pragma unroll
        for (int q = 0; q < 4; q++) {
            int cc = q * 32;
            uint32_t r0[32];
            TCG_LD_X32(r0, tbase + cc);
            TCG_WAIT_LD();
            if (valid) {
                #pragma unroll
                for (int j = 0; j < 32; j += 4) {
                    float4 v;
                    v.x = __uint_as_float(r0[j])     * wgt;
                    v.y = __uint_as_float(r0[j + 1]) * wgt;
                    v.z = __uint_as_float(r0[j + 2]) * wgt;
                    v.w = __uint_as_float(r0[j + 3]) * wgt;
                    *(float4*)(op + cc + j) = v;
                }
            }
        }
    }
    __syncthreads();
    if (wid == 0) TCG_DEALLOC(tmem, 256);
#else
    int tid = threadIdx.x;
    for (int idx = tid; idx < BM2 * BN; idx += 256) {
        int r = row0 + idx / BN;
        if (r >= cnt) continue;
        int cc = col0 + (idx % BN);
        int tokn = g_row_token[off + r];
        int slot = g_row_slot[off + r];
        float wgt = g_row_weight[off + r];
        float acc = 0.0f;
        for (int k = 0; k < Hh; k++) {
            float hv = __bfloat162float(g_hh[(size_t)(off + r) * Hh + k]) +
                       __bfloat162float(g_hl[(size_t)(off + r) * Hh + k]);
            acc += hv * W2[((size_t)e * Dd + cc) * Hh + k];
        }
        g_part[slot][(size_t)tokn * Dd + cc] = acc * wgt;
    }
#endif
}

// ---------------- combine: out = p0 + p1 -----------------------------------
__global__ void combine_kernel(float* __restrict__ out) {
    size_t i = ((size_t)blockIdx.x * blockDim.x + threadIdx.x) * 4;
    size_t stride = (size_t)gridDim.x * blockDim.x * 4;
    for (; i < (size_t)Nn * Dd; i += stride) {
        float4 a = *(const float4*)(&g_part[0][i]);
        float4 b = *(const float4*)(&g_part[1][i]);
        float4 r;
        r.x = a.x + b.x; r.y = a.y + b.y; r.z = a.z + b.z; r.w = a.w + b.w;
        *(float4*)(out + OUT_FINAL + i) = r;
    }
}

// ---------------- v[e] = Wc @ W2[e]  (parallelized) -------------------------
__global__ void vproj_kernel(const float* __restrict__ W2,
                             const float* __restrict__ Wc) {
    int e = blockIdx.y;
    int hbase = blockIdx.x * 64;
    int col = threadIdx.x & 63;
    int seg = threadIdx.x >> 6;       // 0..3
    const float* W2e = W2 + (size_t)e * Dd * Hh;
    float s = 0.0f;
    int d0 = seg * (Dd / 4), d1 = d0 + (Dd / 4);
    #pragma unroll 4
    for (int d = d0; d < d1; d++)
        s += Wc[d] * W2e[(size_t)d * Hh + hbase + col];
    __shared__ float red[4][64];
    red[seg][col] = s;
    __syncthreads();
    if (seg == 0)
        g_v[e * Hh + hbase + col] =
            red[0][col] + red[1][col] + red[2][col] + red[3][col];
}

// ---------------- CLS delta per (batch, slot) ------------------------------
__global__ void cls_kernel() {
    int b = blockIdx.x >> 1;
    int s = blockIdx.x & 1;
    int n = b * Ss;
    int e = g_sel[2*n + s];
    int r = g_slot_row[2*n + s];
    float w = g_selw[2*n + s];
    const __nv_bfloat16* hp = g_hh + (size_t)r * Hh;
    const __nv_bfloat16* lp = g_hl + (size_t)r * Hh;
    const float* vp = g_v + e * Hh;
    float acc = 0.0f;
    for (int i = threadIdx.x; i < Hh; i += blockDim.x)
        acc += (__bfloat162float(hp[i]) + __bfloat162float(lp[i])) * vp[i];
    __shared__ float red[8];
    int lane = threadIdx.x & 31, warp = threadIdx.x >> 5;
    #pragma unroll
    for (int o = 16; o > 0; o >>= 1) acc += __shfl_down_sync(0xffffffffu, acc, o);
    if (lane == 0) red[warp] = acc;
    __syncthreads();
    if (threadIdx.x == 0) {
        float t = 0.0f;
        for (int i = 0; i < (int)(blockDim.x >> 5); i++) t += red[i];
        g_cls_delta[e * Bb + b] = w * t;
    }
}

__global__ void elog_kernel(const float* __restrict__ bc, float* __restrict__ out) {
    int b = threadIdx.x;
    if (b < Bb) {
        float cum = bc[0];
        for (int e = 0; e < Ee; e++) {
            cum += g_cls_delta[e * Bb + b];
            out[OUT_ELOG + e * Bb + b] = cum;
        }
    }
}

// ---------------- host: tensormap encode via driver entry point ------------
typedef CUresult (CUDAAPI *PFN_tme)(
    CUtensorMap*, CUtensorMapDataType, cuuint32_t, void*,
    const cuuint64_t*, const cuuint64_t*, const cuuint32_t*, const cuuint32_t*,
    CUtensorMapInterleave, CUtensorMapSwizzle, CUtensorMapL2promotion,
    CUtensorMapFloatOOBfill);

static void encode_w(PFN_tme enc, CUtensorMap* m, void* base,
                     uint64_t d0, uint64_t d1, uint64_t d2) {
    cuuint64_t dims[3] = {d0, d1, d2};
    cuuint64_t strides[2] = {d0 * 2, d0 * d1 * 2};
    cuuint32_t box[3] = {64, 128, 1};
    cuuint32_t es[3] = {1, 1, 1};
    enc(m, CU_TENSOR_MAP_DATA_TYPE_BFLOAT16, 3, base, dims, strides, box, es,
        CU_TENSOR_MAP_INTERLEAVE_NONE, CU_TENSOR_MAP_SWIZZLE_128B,
        CU_TENSOR_MAP_L2_PROMOTION_L2_128B, CU_TENSOR_MAP_FLOAT_OOB_FILL_NONE);
}

// ---------------- launch ----------------------------------------------------
extern "C" void kernel_launch(void* const* d_in, const int* in_sizes, int n_in,
                              void* d_out, int out_size) {
    const float* x  = (const float*)d_in[0];
    const float* W1 = (const float*)d_in[2];
    const float* W2 = (const float*)d_in[3];
    const float* W3 = (const float*)d_in[4];
    const float* Wg = (const float*)d_in[5];
    const float* Wc = (const float*)d_in[6];
    const float* bc = (const float*)d_in[7];
    float* out = (float*)d_out;

    cudaFuncSetAttribute(ffn1_mma, cudaFuncAttributeMaxDynamicSharedMemorySize, FFN1_SMEM);
    cudaFuncSetAttribute(ffn2_mma, cudaFuncAttributeMaxDynamicSharedMemorySize, FFN2_SMEM);

    __nv_bfloat16 *xh, *xl, *w1h, *w1l, *w3h, *w3l, *w2h, *w2l;
    cudaGetSymbolAddress((void**)&xh,  g_xh);
    cudaGetSymbolAddress((void**)&xl,  g_xl);
    cudaGetSymbolAddress((void**)&w1h, g_w1h);
    cudaGetSymbolAddress((void**)&w1l, g_w1l);
    cudaGetSymbolAddress((void**)&w3h, g_w3h);
    cudaGetSymbolAddress((void**)&w3l, g_w3l);
    cudaGetSymbolAddress((void**)&w2h, g_w2h);
    cudaGetSymbolAddress((void**)&w2l, g_w2l);

    void* pfn = nullptr;
    cudaDriverEntryPointQueryResult qres;
    cudaGetDriverEntryPoint("cuTensorMapEncodeTiled", &pfn,
                            cudaEnableDefault, &qres);
    PFN_tme enc = (PFN_tme)pfn;
    CUtensorMap mW2h, mW2l;
    encode_w(enc, &mW2h, w2h, Hh, Dd, Ee);
    encode_w(enc, &mW2l, w2l, Hh, Dd, Ee);

    init_kernel<<<1, 64>>>();
    gating_kernel<<<Nn, 256>>>(x, Wg, out);
    scan_kernel<<<1, 1>>>();
    scatter_kernel<<<(Nn + 255) / 256, 256>>>();
    split_kernel<<<1024, 256>>>(x,  xh,  xl,  (size_t)Nn * Dd);
    split_kernel<<<2048, 256>>>(W1, w1h, w1l, (size_t)Ee * Hh * Dd);
    split_kernel<<<2048, 256>>>(W3, w3h, w3l, (size_t)Ee * Hh * Dd);
    split_kernel<<<2048, 256>>>(W2, w2h, w2l, (size_t)Ee * Dd * Hh);
    ffn1_mma<<<dim3(Nn / BM, Hh / BN, Ee), 256, FFN1_SMEM>>>(x, W1, W3);
    vproj_kernel<<<dim3(Hh / 64, Ee), 256>>>(W2, Wc);
    ffn2_mma<<<dim3(Nn / BM2, Dd / BN, Ee), 256, FFN2_SMEM>>>(mW2h, mW2l, W2);
    combine_kernel<<<1024, 256>>>(out);
    cls_kernel<<<Bb * 2, 256>>>();
    elog_kernel<<<1, 32>>>(bc, out);
}

// round 11
// speedup vs baseline: 1.1767x; 1.0075x over previous
#include <cuda_runtime.h>
#include <cuda.h>
#include <cuda_bf16.h>
#include <math.h>
#include <cstdint>

// arch guard: tcgen05 only exists on the sm_103a-specific compilation pass
#if !defined(__CUDA_ARCH__) || defined(__CUDA_ARCH_FEAT_SM103_ALL) || \
    (defined(__CUDA_ARCH_SPECIFIC__) && (__CUDA_ARCH_SPECIFIC__ == 1030))
#define USE_TCG 1
#else
#define USE_TCG 0
#endif

// Problem constants
#define Bb 4
#define Ss 1024
#define Dd 1024
#define Hh 2048
#define Ee 8
#define Nn (Bb*Ss)      // 4096 tokens
#define Rr (2*Nn)       // 8192 expert-rows (top-2)

// Output layout (concatenated float32)
#define OUT_FINAL 0
#define OUT_GATE  (Nn*Dd)
#define OUT_ELOG  (OUT_GATE + Nn*Ee)
#define OUT_ROUT  (OUT_ELOG + Ee*Bb)

// ---------------- device scratch ---------------------------------------
__device__ int   g_count[Ee];
__device__ int   g_offset[Ee];
__device__ int   g_cursor[Ee];
__device__ int   g_sel[Nn*2];
__device__ float g_selw[Nn*2];
__device__ int   g_row_token[Rr];
__device__ float g_row_weight[Rr];
__device__ int   g_row_slot[Rr];
__device__ int   g_slot_row[Nn*2];
__device__ float g_v[Ee*Hh];
__device__ float g_cls_delta[Ee*Bb];
__device__ float g_part[2][(size_t)Nn*Dd];             // 32 MB partial sums
// pre-split hi/lo bf16 operands
__device__ __nv_bfloat16 g_xh[(size_t)Nn*Dd];
__device__ __nv_bfloat16 g_xl[(size_t)Nn*Dd];
__device__ __nv_bfloat16 g_w1h[(size_t)Ee*Hh*Dd];
__device__ __nv_bfloat16 g_w1l[(size_t)Ee*Hh*Dd];
__device__ __nv_bfloat16 g_w3h[(size_t)Ee*Hh*Dd];
__device__ __nv_bfloat16 g_w3l[(size_t)Ee*Hh*Dd];
__device__ __nv_bfloat16 g_w2h[(size_t)Ee*Dd*Hh];
__device__ __nv_bfloat16 g_w2l[(size_t)Ee*Dd*Hh];
__device__ __nv_bfloat16 g_hh[(size_t)Rr*Hh];
__device__ __nv_bfloat16 g_hl[(size_t)Rr*Hh];

// ================= inline PTX helpers =====================================
__device__ __forceinline__ uint32_t smem_to_u32(const void* p) {
    uint32_t a;
    asm("{ .reg .u64 t; cvta.to.shared.u64 t, %1; cvt.u32.u64 %0, t; }"
        : "=r"(a) : "l"(p));
    return a;
}
#define CP16(dst, src) \
    asm volatile("cp.async.cg.shared.global [%0], [%1], 16;" \
                 :: "r"((uint32_t)(dst)), "l"(src) : "memory")
#define CP_COMMIT() asm volatile("cp.async.commit_group;" ::: "memory")
#define CP_WAIT0()  asm volatile("cp.async.wait_group 0;" ::: "memory")
#define CP_WAIT1()  asm volatile("cp.async.wait_group 1;" ::: "memory")

#if USE_TCG
__device__ __forceinline__ uint32_t elect_one_pred() {
    uint32_t pred;
    asm volatile("{\n\t.reg .pred p;\n\telect.sync _|p, 0xFFFFFFFF;\n\t"
                 "selp.b32 %0, 1, 0, p;\n\t}" : "=r"(pred));
    return pred;
}
#define TCG_ALLOC(smem_addr, n) \
    asm volatile("tcgen05.alloc.cta_group::1.sync.aligned.shared::cta.b32 [%0], %1;" \
                 :: "r"((uint32_t)(smem_addr)), "r"((uint32_t)(n)) : "memory")
#define TCG_DEALLOC(tmem, n) \
    asm volatile("tcgen05.dealloc.cta_group::1.sync.aligned.b32 %0, %1;" \
                 :: "r"(tmem), "r"((uint32_t)(n)))
#define TCG_RELINQ() \
    asm volatile("tcgen05.relinquish_alloc_permit.cta_group::1.sync.aligned;")
#define TCG_COMMIT(mbar) \
    asm volatile("tcgen05.commit.cta_group::1.mbarrier::arrive::one.shared::cluster.b64 [%0];" \
                 :: "r"((uint32_t)(mbar)) : "memory")
#define TCG_FENCE_AFTER() \
    asm volatile("tcgen05.fence::after_thread_sync;" ::: "memory")
#define TCG_WAIT_LD() \
    asm volatile("tcgen05.wait::ld.sync.aligned;" ::: "memory")
#define FENCE_ASYNC_SHARED() \
    asm volatile("fence.proxy.async.shared::cta;" ::: "memory")
#define MBAR_INIT(mbar, cnt) \
    asm volatile("mbarrier.init.shared.b64 [%0], %1;" \
                 :: "r"((uint32_t)(mbar)), "r"((uint32_t)(cnt)) : "memory")
#define MBAR_WAIT(mbar, parity) do { \
    uint32_t _m = (uint32_t)(mbar); uint32_t _p = (uint32_t)(parity); uint32_t _d; \
    asm volatile("{\n\t.reg .pred p;\n\t" \
        "mbarrier.try_wait.parity.acquire.cta.shared::cta.b64 p, [%1], %2;\n\t" \
        "selp.b32 %0, 1, 0, p;\n\t}" : "=r"(_d) : "r"(_m), "r"(_p) : "memory"); \
    if (!_d) { \
        asm volatile("{\n\t.reg .pred P1;\n\t" \
            "WL_%=:\n\t" \
            "mbarrier.try_wait.parity.acquire.cta.shared::cta.b64 P1, [%0], %1, 0x989680;\n\t" \
            "@P1 bra.uni WD_%=;\n\t" \
            "bra.uni WL_%=;\n\t" \
            "WD_%=:\n\t}" :: "r"(_m), "r"(_p) : "memory"); \
    } \
} while (0)
#define TCG_LD_X32(r, tm) \
    asm volatile("tcgen05.ld.sync.aligned.32x32b.x32.b32 " \
        "{%0, %1, %2, %3, %4, %5, %6, %7, %8, %9, %10, %11, %12, %13, %14, %15, " \
        " %16, %17, %18, %19, %20, %21, %22, %23, %24, %25, %26, %27, %28, %29, %30, %31}, [%32];" \
        : "=r"((r)[0]), "=r"((r)[1]), "=r"((r)[2]), "=r"((r)[3]), \
          "=r"((r)[4]), "=r"((r)[5]), "=r"((r)[6]), "=r"((r)[7]), \
          "=r"((r)[8]), "=r"((r)[9]), "=r"((r)[10]), "=r"((r)[11]), \
          "=r"((r)[12]), "=r"((r)[13]), "=r"((r)[14]), "=r"((r)[15]), \
          "=r"((r)[16]), "=r"((r)[17]), "=r"((r)[18]), "=r"((r)[19]), \
          "=r"((r)[20]), "=r"((r)[21]), "=r"((r)[22]), "=r"((r)[23]), \
          "=r"((r)[24]), "=r"((r)[25]), "=r"((r)[26]), "=r"((r)[27]), \
          "=r"((r)[28]), "=r"((r)[29]), "=r"((r)[30]), "=r"((r)[31]) \
        : "r"(tm))

__device__ __forceinline__ void mma_f16_ss(uint32_t d, uint64_t a, uint64_t b,
                                           uint32_t idesc, bool en) {
    uint32_t e = en ? 1u : 0u;
    asm volatile("{\n\t.reg .pred p;\n\tsetp.ne.u32 p, %5, 0;\n\t"
        "tcgen05.mma.cta_group::1.kind::f16 [%0], %1, %2, %3, {%4, %4, %4, %4}, p;\n\t}"
        :: "r"(d), "l"(a), "l"(b), "r"(idesc), "r"(0u), "r"(e) : "memory");
}

// SW64 smem descriptor: layout=4, version=1, SBO=32, LBO=1
static __device__ __forceinline__ uint64_t make_desc64(uint32_t addr) {
    return ((uint64_t)4 << 61) | ((uint64_t)1 << 46) | ((uint64_t)32 << 32) |
           ((uint64_t)1 << 16) | ((uint64_t)(addr >> 4) & 0x3FFF);
}
#endif // USE_TCG

// idesc: dtype F32, a/b BF16, M=128 (8<<24), N=128 (16<<17)
#define IDESC_128x128 (0x490u | (16u << 17) | (8u << 24))

// GEMM tile constants: BK=32 (SW64 atoms), double-buffered at occ 2
#define BM 128
#define BN 128
#define BK 32
#define BM2 256
// SW64 tile offset for a 128x32 bf16 tile (8KB; atom = 8 rows x 64 bytes)
__device__ __forceinline__ uint32_t tile_off32(int r, int c) {
    uint32_t off = (uint32_t)((r >> 3) * 512 + (r & 7) * 64 + c * 2);
    return off ^ ((off >> 3) & 0x30u);
}

// SMEM maps: 6 tiles x 8KB per stage, 2 stages, occ 2
#define T_SZ 8192
#define STG_SZ (6*T_SZ)               // 48 KB
#define HDR 1536                      // tmem@0, mma mbar[2]@8/16, idx@512
#define FFN_SMEM (HDR + 2*STG_SZ)     // 99840 <= 114688

// ---------------- init: counters only --------------------------------------
__global__ void init_kernel() {
    if (threadIdx.x < Ee) { g_count[threadIdx.x] = 0; g_cursor[threadIdx.x] = 0; }
    if (threadIdx.x < Ee * Bb) g_cls_delta[threadIdx.x] = 0.0f;
}

// ---------------- fused fp32 -> bf16 hi/lo split (all 4 arrays) -----------
__device__ __forceinline__ void split_range(const float* __restrict__ s,
                                            __nv_bfloat16* __restrict__ hi,
                                            __nv_bfloat16* __restrict__ lo,
                                            size_t n, size_t base, size_t stride) {
    for (size_t i = base; i < n; i += stride) {
        float4 v0 = *(const float4*)(s + i);
        float4 v1 = *(const float4*)(s + i + 4);
        float f[8] = {v0.x, v0.y, v0.z, v0.w, v1.x, v1.y, v1.z, v1.w};
        uint16_t hb[8], lb[8];
        #pragma unroll
        for (int j = 0; j < 8; j++) {
            __nv_bfloat16 h = __float2bfloat16_rn(f[j]);
            __nv_bfloat16 l = __float2bfloat16_rn(f[j] - __bfloat162float(h));
            hb[j] = *(uint16_t*)&h;  lb[j] = *(uint16_t*)&l;
        }
        uint4 hv, lv;
        hv.x = ((uint32_t)hb[1] << 16) | hb[0];
        hv.y = ((uint32_t)hb[3] << 16) | hb[2];
        hv.z = ((uint32_t)hb[5] << 16) | hb[4];
        hv.w = ((uint32_t)hb[7] << 16) | hb[6];
        lv.x = ((uint32_t)lb[1] << 16) | lb[0];
        lv.y = ((uint32_t)lb[3] << 16) | lb[2];
        lv.z = ((uint32_t)lb[5] << 16) | lb[4];
        lv.w = ((uint32_t)lb[7] << 16) | lb[6];
        *(uint4*)(hi + i) = hv;
        *(uint4*)(lo + i) = lv;
    }
}

__global__ void split_all_kernel(const float* __restrict__ x,
                                 const float* __restrict__ W1,
                                 const float* __restrict__ W3,
                                 const float* __restrict__ W2) {
    size_t base = ((size_t)blockIdx.x * blockDim.x + threadIdx.x) * 8;
    size_t stride = (size_t)gridDim.x * blockDim.x * 8;
    split_range(x,  g_xh,  g_xl,  (size_t)Nn * Dd,      base, stride);
    split_range(W1, g_w1h, g_w1l, (size_t)Ee * Hh * Dd, base, stride);
    split_range(W3, g_w3h, g_w3l, (size_t)Ee * Hh * Dd, base, stride);
    split_range(W2, g_w2h, g_w2l, (size_t)Ee * Dd * Hh, base, stride);
}

// ---------------- gating --------------------------------------------------
__global__ void gating_kernel(const float* __restrict__ x,
                              const float* __restrict__ Wg,
                              float* __restrict__ out) {
    int n = blockIdx.x;
    __shared__ float xs[Dd];
    __shared__ float logits[Ee];
    for (int i = threadIdx.x; i < Dd; i += blockDim.x)
        xs[i] = x[(size_t)n * Dd + i];
    __syncthreads();
    int warp = threadIdx.x >> 5, lane = threadIdx.x & 31;
    const float* w = Wg + warp * Dd;
    float s = 0.0f;
    for (int i = lane; i < Dd; i += 32) s += xs[i] * w[i];
    #pragma unroll
    for (int o = 16; o > 0; o >>= 1) s += __shfl_down_sync(0xffffffffu, s, o);
    if (lane == 0) logits[warp] = s;
    __syncthreads();
    if (threadIdx.x == 0) {
        float m = logits[0];
        #pragma unroll
        for (int e = 1; e < Ee; e++) m = fmaxf(m, logits[e]);
        float p[Ee]; float den = 0.0f;
        #pragma unroll
        for (int e = 0; e < Ee; e++) { p[e] = expf(logits[e] - m); den += p[e]; }
        float inv = 1.0f / den;
        #pragma unroll
        for (int e = 0; e < Ee; e++) {
            p[e] *= inv;
            out[OUT_GATE + n * Ee + e] = logits[e];
            out[OUT_ROUT + n * Ee + e] = p[e];
        }
        int i0 = 0;
        #pragma unroll
        for (int e = 1; e < Ee; e++) if (p[e] > p[i0]) i0 = e;
        int i1 = (i0 == 0) ? 1 : 0;
        #pragma unroll
        for (int e = 0; e < Ee; e++) if (e != i0 && p[e] > p[i1]) i1 = e;
        float sw = p[i0] + p[i1];
        g_sel[2*n] = i0;  g_sel[2*n+1] = i1;
        g_selw[2*n] = p[i0] / sw;  g_selw[2*n+1] = p[i1] / sw;
        atomicAdd(&g_count[i0], 1);
        atomicAdd(&g_count[i1], 1);
    }
}

__global__ void scan_kernel() {
    int o = 0;
    for (int e = 0; e < Ee; e++) { g_offset[e] = o; o += g_count[e]; }
}

__global__ void scatter_kernel() {
    int n = blockIdx.x * blockDim.x + threadIdx.x;
    if (n >= Nn) return;
    #pragma unroll
    for (int s = 0; s < 2; s++) {
        int e = g_sel[2*n + s];
        int pos = atomicAdd(&g_cursor[e], 1);
        int r = g_offset[e] + pos;
        g_row_token[r] = n;
        g_row_weight[r] = g_selw[2*n + s];
        g_row_slot[r] = s;
        g_slot_row[2*n + s] = r;
    }
}

// =================== FFN1: BK=32, double-buffered, occ 2 ===================
__global__ __launch_bounds__(256, 2) void ffn1_mma(
    const float* __restrict__ x,
    const float* __restrict__ W1,
    const float* __restrict__ W3) {
    int e = blockIdx.z;
    int cnt = g_count[e];
    int row0 = blockIdx.x * BM;
    if (row0 >= cnt) return;
    int off = g_offset[e];
    int col0 = blockIdx.y * BN;

#if USE_TCG
    extern __shared__ __align__(1024) char smem[];
    uint32_t sb = smem_to_u32(smem);
    int tid = threadIdx.x, wid = tid >> 5, lid = tid & 31;

    int* tok = (int*)(smem + 512);
    if (tid < 128) tok[tid] = g_row_token[off + min(row0 + tid, cnt - 1)];
    if (wid == 0) TCG_ALLOC(sb + 0, 256);
    if (tid == 0) { MBAR_INIT(sb + 8, 1); MBAR_INIT(sb + 16, 1); }
    __syncthreads();
    uint32_t tmem;
    asm volatile("ld.shared.b32 %0, [%1];" : "=r"(tmem) : "r"(sb + 0));
    if (wid == 0) TCG_RELINQ();

    // per-thread fill coords (2 slots of 16B per tile)
    int r0s = tid >> 1,  c0s = (tid & 1) << 4;           // slot tid
    int r1s = (tid + 256) >> 1, c1s = ((tid + 256) & 1) << 4;
    // 128 rows x 32 cols: 64B/row => 4 x16B per row; 512 slots
    // slot s: r = s>>2, c = (s&3)*8
    int ra = tid >> 2,  ca = (tid & 3) << 3;
    int rb = (tid + 256) >> 2, cb = ((tid + 256) & 3) << 3;
    (void)r0s; (void)c0s; (void)r1s; (void)c1s;
    uint32_t offa = tile_off32(ra, ca);
    uint32_t offb = tile_off32(rb, cb);

    const int KCH = Dd / BK;      // 32

    auto fill = [&](int f) {
        int st = f & 1;
        int k0 = f * BK;
        uint32_t base = sb + HDR + st * STG_SZ;
        size_t axa = (size_t)tok[ra] * Dd + k0 + ca;
        size_t axb = (size_t)tok[rb] * Dd + k0 + cb;
        size_t wxa = ((size_t)e * Hh + col0 + ra) * Dd + k0 + ca;
        size_t wxb = ((size_t)e * Hh + col0 + rb) * Dd + k0 + cb;
        CP16(base + offa,          g_xh  + axa);
        CP16(base + offb,          g_xh  + axb);
        CP16(base + T_SZ + offa,   g_xl  + axa);
        CP16(base + T_SZ + offb,   g_xl  + axb);
        CP16(base + 2*T_SZ + offa, g_w1h + wxa);
        CP16(base + 2*T_SZ + offb, g_w1h + wxb);
        CP16(base + 3*T_SZ + offa, g_w1l + wxa);
        CP16(base + 3*T_SZ + offb, g_w1l + wxb);
        CP16(base + 4*T_SZ + offa, g_w3h + wxa);
        CP16(base + 4*T_SZ + offb, g_w3h + wxb);
        CP16(base + 5*T_SZ + offa, g_w3l + wxa);
        CP16(base + 5*T_SZ + offb, g_w3l + wxb);
        CP_COMMIT();
    };

    fill(0);
    for (int c = 0; c < KCH; c++) {
        int st = c & 1;
        if (c + 1 < KCH) {
            if (c + 1 >= 2)
                MBAR_WAIT(sb + 8 + ((c + 1) & 1) * 8, ((((c + 1) >> 1) - 1) & 1));
            fill(c + 1);
            CP_WAIT1();
        } else {
            CP_WAIT0();
        }
        FENCE_ASYNC_SHARED();
        __syncthreads();
        if (wid == 0 && elect_one_pred()) {
            uint32_t base = sb + HDR + st * STG_SZ;
            uint64_t dAH  = make_desc64(base);
            uint64_t dAL  = make_desc64(base + T_SZ);
            uint64_t dB1H = make_desc64(base + 2*T_SZ);
            uint64_t dB1L = make_desc64(base + 3*T_SZ);
            uint64_t dB3H = make_desc64(base + 4*T_SZ);
            uint64_t dB3L = make_desc64(base + 5*T_SZ);
            #pragma unroll
            for (int s = 0; s < 2; s++) {
                uint64_t o = (uint64_t)(s * 2);
                bool first = (c == 0) && (s == 0);
                mma_f16_ss(tmem + 0,   dAH + o, dB1H + o, IDESC_128x128, !first);
                mma_f16_ss(tmem + 0,   dAH + o, dB1L + o, IDESC_128x128, true);
                mma_f16_ss(tmem + 0,   dAL + o, dB1H + o, IDESC_128x128, true);
                mma_f16_ss(tmem + 128, dAH + o, dB3H + o, IDESC_128x128, !first);
                mma_f16_ss(tmem + 128, dAH + o, dB3L + o, IDESC_128x128, true);
                mma_f16_ss(tmem + 128, dAL + o, dB3H + o, IDESC_128x128, true);
            }
            TCG_COMMIT(sb + 8 + st * 8);
        }
    }
    MBAR_WAIT(sb + 8,  ((KCH / 2) - 1) & 1);
    MBAR_WAIT(sb + 16, ((KCH / 2) - 1) & 1);
    TCG_FENCE_AFTER();

    // epilogue: silu(z)*y -> hi/lo bf16 h
    {
        int sub = wid & 3;
        int colh = (wid >> 2) * 64;
        int gr = row0 + sub * 32 + lid;
        bool valid = gr < cnt;
        size_t hbase = (size_t)(off + gr) * Hh + col0;
        #pragma unroll
        for (int half = 0; half < 2; half++) {
            int cc = colh + half * 32;
            uint32_t r1[32], r3[32];
            TCG_LD_X32(r1, tmem + cc);
            TCG_LD_X32(r3, tmem + 128 + cc);
            TCG_WAIT_LD();
            if (valid) {
                #pragma unroll
                for (int j = 0; j < 32; j += 2) {
                    float z0 = __uint_as_float(r1[j]);
                    float z1 = __uint_as_float(r1[j + 1]);
                    float h0 = z0 * (1.0f/(1.0f+__expf(-z0))) * __uint_as_float(r3[j]);
                    float h1 = z1 * (1.0f/(1.0f+__expf(-z1))) * __uint_as_float(r3[j+1]);
                    __nv_bfloat16 h0h = __float2bfloat16_rn(h0);
                    __nv_bfloat16 h1h = __float2bfloat16_rn(h1);
                    __nv_bfloat16 h0l = __float2bfloat16_rn(h0 - __bfloat162float(h0h));
                    __nv_bfloat16 h1l = __float2bfloat16_rn(h1 - __bfloat162float(h1h));
                    uint32_t hp = ((uint32_t)*(uint16_t*)&h1h << 16) | *(uint16_t*)&h0h;
                    uint32_t lp = ((uint32_t)*(uint16_t*)&h1l << 16) | *(uint16_t*)&h0l;
                    *(uint32_t*)(g_hh + hbase + cc + j) = hp;
                    *(uint32_t*)(g_hl + hbase + cc + j) = lp;
                }
            }
        }
    }
    __syncthreads();
    if (wid == 0) TCG_DEALLOC(tmem, 256);
#else
    int tid = threadIdx.x;
    for (int idx = tid; idx < BM * BN; idx += 256) {
        int r = row0 + idx / BN;
        if (r >= cnt) continue;
        int cc = col0 + (idx % BN);
        int tokn = g_row_token[off + r];
        float a1 = 0.0f, a3 = 0.0f;
        for (int k = 0; k < Dd; k++) {
            float xv = x[(size_t)tokn * Dd + k];
            a1 += xv * W1[((size_t)e * Hh + cc) * Dd + k];
            a3 += xv * W3[((size_t)e * Hh + cc) * Dd + k];
        }
        float hv = a1 * (1.0f / (1.0f + __expf(-a1))) * a3;
        __nv_bfloat16 hh = __float2bfloat16_rn(hv);
        g_hh[(size_t)(off + r) * Hh + cc] = hh;
        g_hl[(size_t)(off + r) * Hh + cc] =
            __float2bfloat16_rn(hv - __bfloat162float(hh));
    }
#endif
}

// =================== FFN2: BM2=256, BK=32, double-buffered, occ 2 ==========
__global__ __launch_bounds__(256, 2) void ffn2_mma(const float* __restrict__ W2) {
    int e = blockIdx.z;
    int cnt = g_count[e];
    int row0 = blockIdx.x * BM2;
    if (row0 >= cnt) return;
    int off = g_offset[e];
    int col0 = blockIdx.y * BN;

#if USE_TCG
    extern __shared__ __align__(1024) char smem[];
    uint32_t sb = smem_to_u32(smem);
    int tid = threadIdx.x, wid = tid >> 5, lid = tid & 31;

    int* arow = (int*)(smem + 512);
    arow[tid] = off + min(row0 + tid, cnt - 1);
    if (wid == 0) TCG_ALLOC(sb + 0, 256);
    if (tid == 0) { MBAR_INIT(sb + 8, 1); MBAR_INIT(sb + 16, 1); }
    __syncthreads();
    uint32_t tmem;
    asm volatile("ld.shared.b32 %0, [%1];" : "=r"(tmem) : "r"(sb + 0));
    if (wid == 0) TCG_RELINQ();

    int ra = tid >> 2,  ca = (tid & 3) << 3;
    int rb = (tid + 256) >> 2, cb = ((tid + 256) & 3) << 3;
    uint32_t offa = tile_off32(ra, ca);
    uint32_t offb = tile_off32(rb, cb);

    const int KCH = Hh / BK;      // 64

    auto fill = [&](int f) {
        int st = f & 1;
        int k0 = f * BK;
        uint32_t base = sb + HDR + st * STG_SZ;
        size_t a0a = (size_t)arow[ra] * Hh + k0 + ca;
        size_t a0b = (size_t)arow[rb] * Hh + k0 + cb;
        size_t a1a = (size_t)arow[ra + 128] * Hh + k0 + ca;
        size_t a1b = (size_t)arow[rb + 128] * Hh + k0 + cb;
        size_t wxa = ((size_t)e * Dd + col0 + ra) * Hh + k0 + ca;
        size_t wxb = ((size_t)e * Dd + col0 + rb) * Hh + k0 + cb;
        CP16(base + offa,          g_hh + a0a);
        CP16(base + offb,          g_hh + a0b);
        CP16(base + T_SZ + offa,   g_hl + a0a);
        CP16(base + T_SZ + offb,   g_hl + a0b);
        CP16(base + 2*T_SZ + offa, g_hh + a1a);
        CP16(base + 2*T_SZ + offb, g_hh + a1b);
        CP16(base + 3*T_SZ + offa, g_hl + a1a);
        CP16(base + 3*T_SZ + offb, g_hl + a1b);
        CP16(base + 4*T_SZ + offa, g_w2h + wxa);
        CP16(base + 4*T_SZ + offb, g_w2h + wxb);
        CP16(base + 5*T_SZ + offa, g_w2l + wxa);
        CP16(base + 5*T_SZ + offb, g_w2l + wxb);
        CP_COMMIT();
    };

    fill(0);
    for (int c = 0; c < KCH; c++) {
        int st = c & 1;
        if (c + 1 < KCH) {
            if (c + 1 >= 2)
                MBAR_WAIT(sb + 8 + ((c + 1) & 1) * 8, ((((c + 1) >> 1) - 1) & 1));
            fill(c + 1);
            CP_WAIT1();
        } else {
            CP_WAIT0();
        }
        FENCE_ASYNC_SHARED();
        __syncthreads();
        if (wid == 0 && elect_one_pred()) {
            uint32_t base = sb + HDR + st * STG_SZ;
            uint64_t dA0H = make_desc64(base);
            uint64_t dA0L = make_desc64(base + T_SZ);
            uint64_t dA1H = make_desc64(base + 2*T_SZ);
            uint64_t dA1L = make_desc64(base + 3*T_SZ);
            uint64_t dBH  = make_desc64(base + 4*T_SZ);
            uint64_t dBL  = make_desc64(base + 5*T_SZ);
            #pragma unroll
            for (int s = 0; s < 2; s++) {
                uint64_t o = (uint64_t)(s * 2);
                bool first = (c == 0) && (s == 0);
                mma_f16_ss(tmem + 0,   dA0H + o, dBH + o, IDESC_128x128, !first);
                mma_f16_ss(tmem + 0,   dA0H + o, dBL + o, IDESC_128x128, true);
                mma_f16_ss(tmem + 0,   dA0L + o, dBH + o, IDESC_128x128, true);
                mma_f16_ss(tmem + 128, dA1H + o, dBH + o, IDESC_128x128, !first);
                mma_f16_ss(tmem + 128, dA1H + o, dBL + o, IDESC_128x128, true);
                mma_f16_ss(tmem + 128, dA1L + o, dBH + o, IDESC_128x128, true);
            }
            TCG_COMMIT(sb + 8 + st * 8);
        }
    }
    MBAR_WAIT(sb + 8,  ((KCH / 2) - 1) & 1);
    MBAR_WAIT(sb + 16, ((KCH / 2) - 1) & 1);
    TCG_FENCE_AFTER();

    {
        int mblk = wid >> 2;
        int sub = wid & 3;
        int gr = row0 + mblk * 128 + sub * 32 + lid;
        bool valid = gr < cnt;
        int tokn = valid ? g_row_token[off + gr] : 0;
        int slot = valid ? g_row_slot[off + gr] : 0;
        float wgt = valid ? g_row_weight[off + gr] : 0.0f;
        float* op = &g_part[slot][(size_t)tokn * Dd + col0];
        uint32_t tbase = tmem + mblk * 128;
        #pragma unroll
        for (int q = 0; q < 4; q++) {
            int cc = q * 32;
            uint32_t r0[32];
            TCG_LD_X32(r0, tbase + cc);
            TCG_WAIT_LD();
            if (valid) {
                #pragma unroll
                for (int j = 0; j < 32; j += 4) {
                    float4 v;
                    v.x = __uint_as_float(r0[j])     * wgt;
                    v.y = __uint_as_float(r0[j + 1]) * wgt;
                    v.z = __uint_as_float(r0[j + 2]) * wgt;
                    v.w = __uint_as_float(r0[j + 3]) * wgt;
                    *(float4*)(op + cc + j) = v;
                }
            }
        }
    }
    __syncthreads();
    if (wid == 0) TCG_DEALLOC(tmem, 256);
#else
    int tid = threadIdx.x;
    for (int idx = tid; idx < BM2 * BN; idx += 256) {
        int r = row0 + idx / BN;
        if (r >= cnt) continue;
        int cc = col0 + (idx % BN);
        int tokn = g_row_token[off + r];
        int slot = g_row_slot[off + r];
        float wgt = g_row_weight[off + r];
        float acc = 0.0f;
        for (int k = 0; k < Hh; k++) {
            float hv = __bfloat162float(g_hh[(size_t)(off + r) * Hh + k]) +
                       __bfloat162float(g_hl[(size_t)(off + r) * Hh + k]);
            acc += hv * W2[((size_t)e * Dd + cc) * Hh + k];
        }
        g_part[slot][(size_t)tokn * Dd + cc] = acc * wgt;
    }
#endif
}

// ---------------- combine: out = p0 + p1 -----------------------------------
__global__ void combine_kernel(float* __restrict__ out) {
    size_t i = ((size_t)blockIdx.x * blockDim.x + threadIdx.x) * 4;
    size_t stride = (size_t)gridDim.x * blockDim.x * 4;
    for (; i < (size_t)Nn * Dd; i += stride) {
        float4 a = *(const float4*)(&g_part[0][i]);
        float4 b = *(const float4*)(&g_part[1][i]);
        float4 r;
        r.x = a.x + b.x; r.y = a.y + b.y; r.z = a.z + b.z; r.w = a.w + b.w;
        *(float4*)(out + OUT_FINAL + i) = r;
    }
}

// ---------------- v[e] = Wc @ W2[e]  (parallelized) -------------------------
__global__ void vproj_kernel(const float* __restrict__ W2,
                             const float* __restrict__ Wc) {
    int e = blockIdx.y;
    int hbase = blockIdx.x * 64;
    int col = threadIdx.x & 63;
    int seg = threadIdx.x >> 6;
    const float* W2e = W2 + (size_t)e * Dd * Hh;
    float s = 0.0f;
    int d0 = seg * (Dd / 4), d1 = d0 + (Dd / 4);
    #pragma unroll 4
    for (int d = d0; d < d1; d++)
        s += Wc[d] * W2e[(size_t)d * Hh + hbase + col];
    __shared__ float red[4][64];
    red[seg][col] = s;
    __syncthreads();
    if (seg == 0)
        g_v[e * Hh + hbase + col] =
            red[0][col] + red[1][col] + red[2][col] + red[3][col];
}

// ---------------- CLS delta per (batch, slot) ------------------------------
__global__ void cls_kernel() {
    int b = blockIdx.x >> 1;
    int s = blockIdx.x & 1;
    int n = b * Ss;
    int e = g_sel[2*n + s];
    int r = g_slot_row[2*n + s];
    float w = g_selw[2*n + s];
    const __nv_bfloat16* hp = g_hh + (size_t)r * Hh;
    const __nv_bfloat16* lp = g_hl + (size_t)r * Hh;
    const float* vp = g_v + e * Hh;
    float acc = 0.0f;
    for (int i = threadIdx.x; i < Hh; i += blockDim.x)
        acc += (__bfloat162float(hp[i]) + __bfloat162float(lp[i])) * vp[i];
    __shared__ float red[8];
    int lane = threadIdx.x & 31, warp = threadIdx.x >> 5;
    #pragma unroll
    for (int o = 16; o > 0; o >>= 1) acc += __shfl_down_sync(0xffffffffu, acc, o);
    if (lane == 0) red[warp] = acc;
    __syncthreads();
    if (threadIdx.x == 0) {
        float t = 0.0f;
        for (int i = 0; i < (int)(blockDim.x >> 5); i++) t += red[i];
        g_cls_delta[e * Bb + b] = w * t;
    }
}

__global__ void elog_kernel(const float* __restrict__ bc, float* __restrict__ out) {
    int b = threadIdx.x;
    if (b < Bb) {
        float cum = bc[0];
        for (int e = 0; e < Ee; e++) {
            cum += g_cls_delta[e * Bb + b];
            out[OUT_ELOG + e * Bb + b] = cum;
        }
    }
}

// ---------------- launch ----------------------------------------------------
extern "C" void kernel_launch(void* const* d_in, const int* in_sizes, int n_in,
                              void* d_out, int out_size) {
    const float* x  = (const float*)d_in[0];
    const float* W1 = (const float*)d_in[2];
    const float* W2 = (const float*)d_in[3];
    const float* W3 = (const float*)d_in[4];
    const float* Wg = (const float*)d_in[5];
    const float* Wc = (const float*)d_in[6];
    const float* bc = (const float*)d_in[7];
    float* out = (float*)d_out;

    cudaFuncSetAttribute(ffn1_mma, cudaFuncAttributeMaxDynamicSharedMemorySize, FFN_SMEM);
    cudaFuncSetAttribute(ffn2_mma, cudaFuncAttributeMaxDynamicSharedMemorySize, FFN_SMEM);

    init_kernel<<<1, 64>>>();
    gating_kernel<<<Nn, 256>>>(x, Wg, out);
    scan_kernel<<<1, 1>>>();
    scatter_kernel<<<(Nn + 255) / 256, 256>>>();
    split_all_kernel<<<2048, 256>>>(x, W1, W3, W2);
    ffn1_mma<<<dim3(Nn / BM, Hh / BN, Ee), 256, FFN_SMEM>>>(x, W1, W3);
    vproj_kernel<<<dim3(Hh / 64, Ee), 256>>>(W2, Wc);
    ffn2_mma<<<dim3(Nn / BM2, Dd / BN, Ee), 256, FFN_SMEM>>>(W2);
    combine_kernel<<<1024, 256>>>(out);
    cls_kernel<<<Bb * 2, 256>>>();
    elog_kernel<<<1, 32>>>(bc, out);
}

// round 12
// speedup vs baseline: 1.1788x; 1.0018x over previous
#include <cuda_runtime.h>
#include <cuda.h>
#include <cuda_bf16.h>
#include <math.h>
#include <cstdint>

// arch guard: tcgen05 only exists on the sm_103a-specific compilation pass
#if !defined(__CUDA_ARCH__) || defined(__CUDA_ARCH_FEAT_SM103_ALL) || \
    (defined(__CUDA_ARCH_SPECIFIC__) && (__CUDA_ARCH_SPECIFIC__ == 1030))
#define USE_TCG 1
#else
#define USE_TCG 0
#endif

// Problem constants
#define Bb 4
#define Ss 1024
#define Dd 1024
#define Hh 2048
#define Ee 8
#define Nn (Bb*Ss)      // 4096 tokens
#define Rr (2*Nn)       // 8192 expert-rows (top-2)

// Output layout (concatenated float32)
#define OUT_FINAL 0
#define OUT_GATE  (Nn*Dd)
#define OUT_ELOG  (OUT_GATE + Nn*Ee)
#define OUT_ROUT  (OUT_ELOG + Ee*Bb)

// ---------------- device scratch ---------------------------------------
__device__ int   g_count[Ee];
__device__ int   g_offset[Ee];
__device__ int   g_cursor[Ee];
__device__ int   g_sel[Nn*2];
__device__ float g_selw[Nn*2];
__device__ int   g_row_token[Rr];
__device__ float g_row_weight[Rr];
__device__ int   g_row_slot[Rr];
__device__ int   g_slot_row[Nn*2];
__device__ float g_v[Ee*Hh];
__device__ float g_cls_delta[Ee*Bb];
__device__ float g_part[2][(size_t)Nn*Dd];             // 32 MB partial sums
// pre-split hi/lo bf16 operands
__device__ __nv_bfloat16 g_xh[(size_t)Nn*Dd];
__device__ __nv_bfloat16 g_xl[(size_t)Nn*Dd];
__device__ __nv_bfloat16 g_w1h[(size_t)Ee*Hh*Dd];
__device__ __nv_bfloat16 g_w1l[(size_t)Ee*Hh*Dd];
__device__ __nv_bfloat16 g_w3h[(size_t)Ee*Hh*Dd];
__device__ __nv_bfloat16 g_w3l[(size_t)Ee*Hh*Dd];
__device__ __nv_bfloat16 g_w2h[(size_t)Ee*Dd*Hh];
__device__ __nv_bfloat16 g_w2l[(size_t)Ee*Dd*Hh];
__device__ __nv_bfloat16 g_hh[(size_t)Rr*Hh];
__device__ __nv_bfloat16 g_hl[(size_t)Rr*Hh];

// ================= inline PTX helpers =====================================
__device__ __forceinline__ uint32_t smem_to_u32(const void* p) {
    uint32_t a;
    asm("{ .reg .u64 t; cvta.to.shared.u64 t, %1; cvt.u32.u64 %0, t; }"
        : "=r"(a) : "l"(p));
    return a;
}
#define CP16(dst, src) \
    asm volatile("cp.async.cg.shared.global [%0], [%1], 16;" \
                 :: "r"((uint32_t)(dst)), "l"(src) : "memory")
#define CP_COMMIT() asm volatile("cp.async.commit_group;" ::: "memory")
#define CP_WAIT0()  asm volatile("cp.async.wait_group 0;" ::: "memory")
#define CP_WAIT1()  asm volatile("cp.async.wait_group 1;" ::: "memory")

#if USE_TCG
__device__ __forceinline__ uint32_t elect_one_pred() {
    uint32_t pred;
    asm volatile("{\n\t.reg .pred p;\n\telect.sync _|p, 0xFFFFFFFF;\n\t"
                 "selp.b32 %0, 1, 0, p;\n\t}" : "=r"(pred));
    return pred;
}
#define TCG_ALLOC(smem_addr, n) \
    asm volatile("tcgen05.alloc.cta_group::1.sync.aligned.shared::cta.b32 [%0], %1;" \
                 :: "r"((uint32_t)(smem_addr)), "r"((uint32_t)(n)) : "memory")
#define TCG_DEALLOC(tmem, n) \
    asm volatile("tcgen05.dealloc.cta_group::1.sync.aligned.b32 %0, %1;" \
                 :: "r"(tmem), "r"((uint32_t)(n)))
#define TCG_RELINQ() \
    asm volatile("tcgen05.relinquish_alloc_permit.cta_group::1.sync.aligned;")
#define TCG_COMMIT(mbar) \
    asm volatile("tcgen05.commit.cta_group::1.mbarrier::arrive::one.shared::cluster.b64 [%0];" \
                 :: "r"((uint32_t)(mbar)) : "memory")
#define TCG_FENCE_AFTER() \
    asm volatile("tcgen05.fence::after_thread_sync;" ::: "memory")
#define TCG_WAIT_LD() \
    asm volatile("tcgen05.wait::ld.sync.aligned;" ::: "memory")
#define FENCE_ASYNC_SHARED() \
    asm volatile("fence.proxy.async.shared::cta;" ::: "memory")
#define MBAR_INIT(mbar, cnt) \
    asm volatile("mbarrier.init.shared.b64 [%0], %1;" \
                 :: "r"((uint32_t)(mbar)), "r"((uint32_t)(cnt)) : "memory")
#define MBAR_WAIT(mbar, parity) do { \
    uint32_t _m = (uint32_t)(mbar); uint32_t _p = (uint32_t)(parity); uint32_t _d; \
    asm volatile("{\n\t.reg .pred p;\n\t" \
        "mbarrier.try_wait.parity.acquire.cta.shared::cta.b64 p, [%1], %2;\n\t" \
        "selp.b32 %0, 1, 0, p;\n\t}" : "=r"(_d) : "r"(_m), "r"(_p) : "memory"); \
    if (!_d) { \
        asm volatile("{\n\t.reg .pred P1;\n\t" \
            "WL_%=:\n\t" \
            "mbarrier.try_wait.parity.acquire.cta.shared::cta.b64 P1, [%0], %1, 0x989680;\n\t" \
            "@P1 bra.uni WD_%=;\n\t" \
            "bra.uni WL_%=;\n\t" \
            "WD_%=:\n\t}" :: "r"(_m), "r"(_p) : "memory"); \
    } \
} while (0)
#define TCG_LD_X32(r, tm) \
    asm volatile("tcgen05.ld.sync.aligned.32x32b.x32.b32 " \
        "{%0, %1, %2, %3, %4, %5, %6, %7, %8, %9, %10, %11, %12, %13, %14, %15, " \
        " %16, %17, %18, %19, %20, %21, %22, %23, %24, %25, %26, %27, %28, %29, %30, %31}, [%32];" \
        : "=r"((r)[0]), "=r"((r)[1]), "=r"((r)[2]), "=r"((r)[3]), \
          "=r"((r)[4]), "=r"((r)[5]), "=r"((r)[6]), "=r"((r)[7]), \
          "=r"((r)[8]), "=r"((r)[9]), "=r"((r)[10]), "=r"((r)[11]), \
          "=r"((r)[12]), "=r"((r)[13]), "=r"((r)[14]), "=r"((r)[15]), \
          "=r"((r)[16]), "=r"((r)[17]), "=r"((r)[18]), "=r"((r)[19]), \
          "=r"((r)[20]), "=r"((r)[21]), "=r"((r)[22]), "=r"((r)[23]), \
          "=r"((r)[24]), "=r"((r)[25]), "=r"((r)[26]), "=r"((r)[27]), \
          "=r"((r)[28]), "=r"((r)[29]), "=r"((r)[30]), "=r"((r)[31]) \
        : "r"(tm))

__device__ __forceinline__ void mma_f16_ss(uint32_t d, uint64_t a, uint64_t b,
                                           uint32_t idesc, bool en) {
    uint32_t e = en ? 1u : 0u;
    asm volatile("{\n\t.reg .pred p;\n\tsetp.ne.u32 p, %5, 0;\n\t"
        "tcgen05.mma.cta_group::1.kind::f16 [%0], %1, %2, %3, {%4, %4, %4, %4}, p;\n\t}"
        :: "r"(d), "l"(a), "l"(b), "r"(idesc), "r"(0u), "r"(e) : "memory");
}

// SW64 smem descriptor: layout=4, version=1, SBO=32, LBO=1
static __device__ __forceinline__ uint64_t make_desc64(uint32_t addr) {
    return ((uint64_t)4 << 61) | ((uint64_t)1 << 46) | ((uint64_t)32 << 32) |
           ((uint64_t)1 << 16) | ((uint64_t)(addr >> 4) & 0x3FFF);
}
#endif // USE_TCG

// idesc: dtype F32, a/b BF16, M=128 (8<<24), N=128 (16<<17)
#define IDESC_128x128 (0x490u | (16u << 17) | (8u << 24))

// GEMM tile constants: BK=32 (SW64 atoms), double-buffered at occ 2
#define BM 128
#define BN 128
#define BK 32
#define BM2 256
// SW64 tile offset for a 128x32 bf16 tile (8KB; atom = 8 rows x 64 bytes)
__device__ __forceinline__ uint32_t tile_off32(int r, int c) {
    uint32_t off = (uint32_t)((r >> 3) * 512 + (r & 7) * 64 + c * 2);
    return off ^ ((off >> 3) & 0x30u);
}

// SMEM maps: 6 tiles x 8KB per stage, 2 stages, occ 2
#define T_SZ 8192
#define STG_SZ (6*T_SZ)               // 48 KB
#define HDR 1536                      // tmem@0, mma mbar[2]@8/16, idx@512
#define FFN_SMEM (HDR + 2*STG_SZ)     // 99840 <= 114688

// ---------------- init: counters only --------------------------------------
__global__ void init_kernel() {
    if (threadIdx.x < Ee) { g_count[threadIdx.x] = 0; g_cursor[threadIdx.x] = 0; }
    if (threadIdx.x < Ee * Bb) g_cls_delta[threadIdx.x] = 0.0f;
}

// ---------------- fused fp32 -> bf16 hi/lo split (all 4 arrays) -----------
__device__ __forceinline__ void split_range(const float* __restrict__ s,
                                            __nv_bfloat16* __restrict__ hi,
                                            __nv_bfloat16* __restrict__ lo,
                                            size_t n, size_t base, size_t stride) {
    for (size_t i = base; i < n; i += stride) {
        float4 v0 = *(const float4*)(s + i);
        float4 v1 = *(const float4*)(s + i + 4);
        float f[8] = {v0.x, v0.y, v0.z, v0.w, v1.x, v1.y, v1.z, v1.w};
        uint16_t hb[8], lb[8];
        #pragma unroll
        for (int j = 0; j < 8; j++) {
            __nv_bfloat16 h = __float2bfloat16_rn(f[j]);
            __nv_bfloat16 l = __float2bfloat16_rn(f[j] - __bfloat162float(h));
            hb[j] = *(uint16_t*)&h;  lb[j] = *(uint16_t*)&l;
        }
        uint4 hv, lv;
        hv.x = ((uint32_t)hb[1] << 16) | hb[0];
        hv.y = ((uint32_t)hb[3] << 16) | hb[2];
        hv.z = ((uint32_t)hb[5] << 16) | hb[4];
        hv.w = ((uint32_t)hb[7] << 16) | hb[6];
        lv.x = ((uint32_t)lb[1] << 16) | lb[0];
        lv.y = ((uint32_t)lb[3] << 16) | lb[2];
        lv.z = ((uint32_t)lb[5] << 16) | lb[4];
        lv.w = ((uint32_t)lb[7] << 16) | lb[6];
        *(uint4*)(hi + i) = hv;
        *(uint4*)(lo + i) = lv;
    }
}

__global__ void split_all_kernel(const float* __restrict__ x,
                                 const float* __restrict__ W1,
                                 const float* __restrict__ W3,
                                 const float* __restrict__ W2) {
    size_t base = ((size_t)blockIdx.x * blockDim.x + threadIdx.x) * 8;
    size_t stride = (size_t)gridDim.x * blockDim.x * 8;
    split_range(x,  g_xh,  g_xl,  (size_t)Nn * Dd,      base, stride);
    split_range(W1, g_w1h, g_w1l, (size_t)Ee * Hh * Dd, base, stride);
    split_range(W3, g_w3h, g_w3l, (size_t)Ee * Hh * Dd, base, stride);
    split_range(W2, g_w2h, g_w2l, (size_t)Ee * Dd * Hh, base, stride);
}

// ---------------- gating --------------------------------------------------
__global__ void gating_kernel(const float* __restrict__ x,
                              const float* __restrict__ Wg,
                              float* __restrict__ out) {
    int n = blockIdx.x;
    __shared__ float xs[Dd];
    __shared__ float logits[Ee];
    for (int i = threadIdx.x; i < Dd; i += blockDim.x)
        xs[i] = x[(size_t)n * Dd + i];
    __syncthreads();
    int warp = threadIdx.x >> 5, lane = threadIdx.x & 31;
    const float* w = Wg + warp * Dd;
    float s = 0.0f;
    for (int i = lane; i < Dd; i += 32) s += xs[i] * w[i];
    #pragma unroll
    for (int o = 16; o > 0; o >>= 1) s += __shfl_down_sync(0xffffffffu, s, o);
    if (lane == 0) logits[warp] = s;
    __syncthreads();
    if (threadIdx.x == 0) {
        float m = logits[0];
        #pragma unroll
        for (int e = 1; e < Ee; e++) m = fmaxf(m, logits[e]);
        float p[Ee]; float den = 0.0f;
        #pragma unroll
        for (int e = 0; e < Ee; e++) { p[e] = expf(logits[e] - m); den += p[e]; }
        float inv = 1.0f / den;
        #pragma unroll
        for (int e = 0; e < Ee; e++) {
            p[e] *= inv;
            out[OUT_GATE + n * Ee + e] = logits[e];
            out[OUT_ROUT + n * Ee + e] = p[e];
        }
        int i0 = 0;
        #pragma unroll
        for (int e = 1; e < Ee; e++) if (p[e] > p[i0]) i0 = e;
        int i1 = (i0 == 0) ? 1 : 0;
        #pragma unroll
        for (int e = 0; e < Ee; e++) if (e != i0 && p[e] > p[i1]) i1 = e;
        float sw = p[i0] + p[i1];
        g_sel[2*n] = i0;  g_sel[2*n+1] = i1;
        g_selw[2*n] = p[i0] / sw;  g_selw[2*n+1] = p[i1] / sw;
        atomicAdd(&g_count[i0], 1);
        atomicAdd(&g_count[i1], 1);
    }
}

__global__ void scan_kernel() {
    int o = 0;
    for (int e = 0; e < Ee; e++) { g_offset[e] = o; o += g_count[e]; }
}

__global__ void scatter_kernel() {
    int n = blockIdx.x * blockDim.x + threadIdx.x;
    if (n >= Nn) return;
    #pragma unroll
    for (int s = 0; s < 2; s++) {
        int e = g_sel[2*n + s];
        int pos = atomicAdd(&g_cursor[e], 1);
        int r = g_offset[e] + pos;
        g_row_token[r] = n;
        g_row_weight[r] = g_selw[2*n + s];
        g_row_slot[r] = s;
        g_slot_row[2*n + s] = r;
    }
}

// =================== FFN1: BK=32, double-buffered, occ 2 ===================
__global__ __launch_bounds__(256, 2) void ffn1_mma(
    const float* __restrict__ x,
    const float* __restrict__ W1,
    const float* __restrict__ W3) {
    int e = blockIdx.z;
    int cnt = g_count[e];
    int row0 = blockIdx.x * BM;
    if (row0 >= cnt) return;
    int off = g_offset[e];
    int col0 = blockIdx.y * BN;

#if USE_TCG
    extern __shared__ __align__(1024) char smem[];
    uint32_t sb = smem_to_u32(smem);
    int tid = threadIdx.x, wid = tid >> 5, lid = tid & 31;

    int* tok = (int*)(smem + 512);
    if (tid < 128) tok[tid] = g_row_token[off + min(row0 + tid, cnt - 1)];
    if (wid == 0) TCG_ALLOC(sb + 0, 256);
    if (tid == 0) { MBAR_INIT(sb + 8, 1); MBAR_INIT(sb + 16, 1); }
    __syncthreads();
    uint32_t tmem;
    asm volatile("ld.shared.b32 %0, [%1];" : "=r"(tmem) : "r"(sb + 0));
    if (wid == 0) TCG_RELINQ();

    // per-thread fill coords (2 slots of 16B per tile)
    int r0s = tid >> 1,  c0s = (tid & 1) << 4;           // slot tid
    int r1s = (tid + 256) >> 1, c1s = ((tid + 256) & 1) << 4;
    // 128 rows x 32 cols: 64B/row => 4 x16B per row; 512 slots
    // slot s: r = s>>2, c = (s&3)*8
    int ra = tid >> 2,  ca = (tid & 3) << 3;
    int rb = (tid + 256) >> 2, cb = ((tid + 256) & 3) << 3;
    (void)r0s; (void)c0s; (void)r1s; (void)c1s;
    uint32_t offa = tile_off32(ra, ca);
    uint32_t offb = tile_off32(rb, cb);

    const int KCH = Dd / BK;      // 32

    auto fill = [&](int f) {
        int st = f & 1;
        int k0 = f * BK;
        uint32_t base = sb + HDR + st * STG_SZ;
        size_t axa = (size_t)tok[ra] * Dd + k0 + ca;
        size_t axb = (size_t)tok[rb] * Dd + k0 + cb;
        size_t wxa = ((size_t)e * Hh + col0 + ra) * Dd + k0 + ca;
        size_t wxb = ((size_t)e * Hh + col0 + rb) * Dd + k0 + cb;
        CP16(base + offa,          g_xh  + axa);
        CP16(base + offb,          g_xh  + axb);
        CP16(base + T_SZ + offa,   g_xl  + axa);
        CP16(base + T_SZ + offb,   g_xl  + axb);
        CP16(base + 2*T_SZ + offa, g_w1h + wxa);
        CP16(base + 2*T_SZ + offb, g_w1h + wxb);
        CP16(base + 3*T_SZ + offa, g_w1l + wxa);
        CP16(base + 3*T_SZ + offb, g_w1l + wxb);
        CP16(base + 4*T_SZ + offa, g_w3h + wxa);
        CP16(base + 4*T_SZ + offb, g_w3h + wxb);
        CP16(base + 5*T_SZ + offa, g_w3l + wxa);
        CP16(base + 5*T_SZ + offb, g_w3l + wxb);
        CP_COMMIT();
    };

    fill(0);
    for (int c = 0; c < KCH; c++) {
        int st = c & 1;
        if (c + 1 < KCH) {
            if (c + 1 >= 2)
                MBAR_WAIT(sb + 8 + ((c + 1) & 1) * 8, ((((c + 1) >> 1) - 1) & 1));
            fill(c + 1);
            CP_WAIT1();
        } else {
            CP_WAIT0();
        }
        FENCE_ASYNC_SHARED();
        __syncthreads();
        if (wid == 0 && elect_one_pred()) {
            uint32_t base = sb + HDR + st * STG_SZ;
            uint64_t dAH  = make_desc64(base);
            uint64_t dAL  = make_desc64(base + T_SZ);
            uint64_t dB1H = make_desc64(base + 2*T_SZ);
            uint64_t dB1L = make_desc64(base + 3*T_SZ);
            uint64_t dB3H = make_desc64(base + 4*T_SZ);
            uint64_t dB3L = make_desc64(base + 5*T_SZ);
            #pragma unroll
            for (int s = 0; s < 2; s++) {
                uint64_t o = (uint64_t)(s * 2);
                bool first = (c == 0) && (s == 0);
                mma_f16_ss(tmem + 0,   dAH + o, dB1H + o, IDESC_128x128, !first);
                mma_f16_ss(tmem + 0,   dAH + o, dB1L + o, IDESC_128x128, true);
                mma_f16_ss(tmem + 0,   dAL + o, dB1H + o, IDESC_128x128, true);
                mma_f16_ss(tmem + 128, dAH + o, dB3H + o, IDESC_128x128, !first);
                mma_f16_ss(tmem + 128, dAH + o, dB3L + o, IDESC_128x128, true);
                mma_f16_ss(tmem + 128, dAL + o, dB3H + o, IDESC_128x128, true);
            }
            TCG_COMMIT(sb + 8 + st * 8);
        }
    }
    MBAR_WAIT(sb + 8,  ((KCH / 2) - 1) & 1);
    MBAR_WAIT(sb + 16, ((KCH / 2) - 1) & 1);
    TCG_FENCE_AFTER();

    // epilogue: silu(z)*y -> hi/lo bf16 h
    {
        int sub = wid & 3;
        int colh = (wid >> 2) * 64;
        int gr = row0 + sub * 32 + lid;
        bool valid = gr < cnt;
        size_t hbase = (size_t)(off + gr) * Hh + col0;
        #pragma unroll
        for (int half = 0; half < 2; half++) {
            int cc = colh + half * 32;
            uint32_t r1[32], r3[32];
            TCG_LD_X32(r1, tmem + cc);
            TCG_LD_X32(r3, tmem + 128 + cc);
            TCG_WAIT_LD();
            if (valid) {
                #pragma unroll
                for (int j = 0; j < 32; j += 2) {
                    float z0 = __uint_as_float(r1[j]);
                    float z1 = __uint_as_float(r1[j + 1]);
                    float h0 = z0 * (1.0f/(1.0f+__expf(-z0))) * __uint_as_float(r3[j]);
                    float h1 = z1 * (1.0f/(1.0f+__expf(-z1))) * __uint_as_float(r3[j+1]);
                    __nv_bfloat16 h0h = __float2bfloat16_rn(h0);
                    __nv_bfloat16 h1h = __float2bfloat16_rn(h1);
                    __nv_bfloat16 h0l = __float2bfloat16_rn(h0 - __bfloat162float(h0h));
                    __nv_bfloat16 h1l = __float2bfloat16_rn(h1 - __bfloat162float(h1h));
                    uint32_t hp = ((uint32_t)*(uint16_t*)&h1h << 16) | *(uint16_t*)&h0h;
                    uint32_t lp = ((uint32_t)*(uint16_t*)&h1l << 16) | *(uint16_t*)&h0l;
                    *(uint32_t*)(g_hh + hbase + cc + j) = hp;
                    *(uint32_t*)(g_hl + hbase + cc + j) = lp;
                }
            }
        }
    }
    __syncthreads();
    if (wid == 0) TCG_DEALLOC(tmem, 256);
#else
    int tid = threadIdx.x;
    for (int idx = tid; idx < BM * BN; idx += 256) {
        int r = row0 + idx / BN;
        if (r >= cnt) continue;
        int cc = col0 + (idx % BN);
        int tokn = g_row_token[off + r];
        float a1 = 0.0f, a3 = 0.0f;
        for (int k = 0; k < Dd; k++) {
            float xv = x[(size_t)tokn * Dd + k];
            a1 += xv * W1[((size_t)e * Hh + cc) * Dd + k];
            a3 += xv * W3[((size_t)e * Hh + cc) * Dd + k];
        }
        float hv = a1 * (1.0f / (1.0f + __expf(-a1))) * a3;
        __nv_bfloat16 hh = __float2bfloat16_rn(hv);
        g_hh[(size_t)(off + r) * Hh + cc] = hh;
        g_hl[(size_t)(off + r) * Hh + cc] =
            __float2bfloat16_rn(hv - __bfloat162float(hh));
    }
#endif
}

// =================== FFN2: BM2=256, BK=32, double-buffered, occ 2 ==========
__global__ __launch_bounds__(256, 2) void ffn2_mma(const float* __restrict__ W2) {
    int e = blockIdx.z;
    int cnt = g_count[e];
    int row0 = blockIdx.x * BM2;
    if (row0 >= cnt) return;
    int off = g_offset[e];
    int col0 = blockIdx.y * BN;

#if USE_TCG
    extern __shared__ __align__(1024) char smem[];
    uint32_t sb = smem_to_u32(smem);
    int tid = threadIdx.x, wid = tid >> 5, lid = tid & 31;

    int* arow = (int*)(smem + 512);
    arow[tid] = off + min(row0 + tid, cnt - 1);
    if (wid == 0) TCG_ALLOC(sb + 0, 256);
    if (tid == 0) { MBAR_INIT(sb + 8, 1); MBAR_INIT(sb + 16, 1); }
    __syncthreads();
    uint32_t tmem;
    asm volatile("ld.shared.b32 %0, [%1];" : "=r"(tmem) : "r"(sb + 0));
    if (wid == 0) TCG_RELINQ();

    int ra = tid >> 2,  ca = (tid & 3) << 3;
    int rb = (tid + 256) >> 2, cb = ((tid + 256) & 3) << 3;
    uint32_t offa = tile_off32(ra, ca);
    uint32_t offb = tile_off32(rb, cb);

    const int KCH = Hh / BK;      // 64

    auto fill = [&](int f) {
        int st = f & 1;
        int k0 = f * BK;
        uint32_t base = sb + HDR + st * STG_SZ;
        size_t a0a = (size_t)arow[ra] * Hh + k0 + ca;
        size_t a0b = (size_t)arow[rb] * Hh + k0 + cb;
        size_t a1a = (size_t)arow[ra + 128] * Hh + k0 + ca;
        size_t a1b = (size_t)arow[rb + 128] * Hh + k0 + cb;
        size_t wxa = ((size_t)e * Dd + col0 + ra) * Hh + k0 + ca;
        size_t wxb = ((size_t)e * Dd + col0 + rb) * Hh + k0 + cb;
        CP16(base + offa,          g_hh + a0a);
        CP16(base + offb,          g_hh + a0b);
        CP16(base + T_SZ + offa,   g_hl + a0a);
        CP16(base + T_SZ + offb,   g_hl + a0b);
        CP16(base + 2*T_SZ + offa, g_hh + a1a);
        CP16(base + 2*T_SZ + offb, g_hh + a1b);
        CP16(base + 3*T_SZ + offa, g_hl + a1a);
        CP16(base + 3*T_SZ + offb, g_hl + a1b);
        CP16(base + 4*T_SZ + offa, g_w2h + wxa);
        CP16(base + 4*T_SZ + offb, g_w2h + wxb);
        CP16(base + 5*T_SZ + offa, g_w2l + wxa);
        CP16(base + 5*T_SZ + offb, g_w2l + wxb);
        CP_COMMIT();
    };

    fill(0);
    for (int c = 0; c < KCH; c++) {
        int st = c & 1;
        if (c + 1 < KCH) {
            if (c + 1 >= 2)
                MBAR_WAIT(sb + 8 + ((c + 1) & 1) * 8, ((((c + 1) >> 1) - 1) & 1));
            fill(c + 1);
            CP_WAIT1();
        } else {
            CP_WAIT0();
        }
        FENCE_ASYNC_SHARED();
        __syncthreads();
        if (wid == 0 && elect_one_pred()) {
            uint32_t base = sb + HDR + st * STG_SZ;
            uint64_t dA0H = make_desc64(base);
            uint64_t dA0L = make_desc64(base + T_SZ);
            uint64_t dA1H = make_desc64(base + 2*T_SZ);
            uint64_t dA1L = make_desc64(base + 3*T_SZ);
            uint64_t dBH  = make_desc64(base + 4*T_SZ);
            uint64_t dBL  = make_desc64(base + 5*T_SZ);
            #pragma unroll
            for (int s = 0; s < 2; s++) {
                uint64_t o = (uint64_t)(s * 2);
                bool first = (c == 0) && (s == 0);
                mma_f16_ss(tmem + 0,   dA0H + o, dBH + o, IDESC_128x128, !first);
                mma_f16_ss(tmem + 0,   dA0H + o, dBL + o, IDESC_128x128, true);
                mma_f16_ss(tmem + 0,   dA0L + o, dBH + o, IDESC_128x128, true);
                mma_f16_ss(tmem + 128, dA1H + o, dBH + o, IDESC_128x128, !first);
                mma_f16_ss(tmem + 128, dA1H + o, dBL + o, IDESC_128x128, true);
                mma_f16_ss(tmem + 128, dA1L + o, dBH + o, IDESC_128x128, true);
            }
            TCG_COMMIT(sb + 8 + st * 8);
        }
    }
    MBAR_WAIT(sb + 8,  ((KCH / 2) - 1) & 1);
    MBAR_WAIT(sb + 16, ((KCH / 2) - 1) & 1);
    TCG_FENCE_AFTER();

    {
        int mblk = wid >> 2;
        int sub = wid & 3;
        int gr = row0 + mblk * 128 + sub * 32 + lid;
        bool valid = gr < cnt;
        int tokn = valid ? g_row_token[off + gr] : 0;
        int slot = valid ? g_row_slot[off + gr] : 0;
        float wgt = valid ? g_row_weight[off + gr] : 0.0f;
        float* op = &g_part[slot][(size_t)tokn * Dd + col0];
        uint32_t tbase = tmem + mblk * 128;
        #pragma unroll
        for (int q = 0; q < 4; q++) {
            int cc = q * 32;
            uint32_t r0[32];
            TCG_LD_X32(r0, tbase + cc);
            TCG_WAIT_LD();
            if (valid) {
                #pragma unroll
                for (int j = 0; j < 32; j += 4) {
                    float4 v;
                    v.x = __uint_as_float(r0[j])     * wgt;
                    v.y = __uint_as_float(r0[j + 1]) * wgt;
                    v.z = __uint_as_float(r0[j + 2]) * wgt;
                    v.w = __uint_as_float(r0[j + 3]) * wgt;
                    *(float4*)(op + cc + j) = v;
                }
            }
        }
    }
    __syncthreads();
    if (wid == 0) TCG_DEALLOC(tmem, 256);
#else
    int tid = threadIdx.x;
    for (int idx = tid; idx < BM2 * BN; idx += 256) {
        int r = row0 + idx / BN;
        if (r >= cnt) continue;
        int cc = col0 + (idx % BN);
        int tokn = g_row_token[off + r];
        int slot = g_row_slot[off + r];
        float wgt = g_row_weight[off + r];
        float acc = 0.0f;
        for (int k = 0; k < Hh; k++) {
            float hv = __bfloat162float(g_hh[(size_t)(off + r) * Hh + k]) +
                       __bfloat162float(g_hl[(size_t)(off + r) * Hh + k]);
            acc += hv * W2[((size_t)e * Dd + cc) * Hh + k];
        }
        g_part[slot][(size_t)tokn * Dd + cc] = acc * wgt;
    }
#endif
}

// ---------------- combine: out = p0 + p1 -----------------------------------
__global__ void combine_kernel(float* __restrict__ out) {
    size_t i = ((size_t)blockIdx.x * blockDim.x + threadIdx.x) * 4;
    size_t stride = (size_t)gridDim.x * blockDim.x * 4;
    for (; i < (size_t)Nn * Dd; i += stride) {
        float4 a = *(const float4*)(&g_part[0][i]);
        float4 b = *(const float4*)(&g_part[1][i]);
        float4 r;
        r.x = a.x + b.x; r.y = a.y + b.y; r.z = a.z + b.z; r.w = a.w + b.w;
        *(float4*)(out + OUT_FINAL + i) = r;
    }
}

// ---------------- v[e] = Wc @ W2[e]  (parallelized) -------------------------
__global__ void vproj_kernel(const float* __restrict__ W2,
                             const float* __restrict__ Wc) {
    int e = blockIdx.y;
    int hbase = blockIdx.x * 64;
    int col = threadIdx.x & 63;
    int seg = threadIdx.x >> 6;
    const float* W2e = W2 + (size_t)e * Dd * Hh;
    float s = 0.0f;
    int d0 = seg * (Dd / 4), d1 = d0 + (Dd / 4);
    #pragma unroll 4
    for (int d = d0; d < d1; d++)
        s += Wc[d] * W2e[(size_t)d * Hh + hbase + col];
    __shared__ float red[4][64];
    red[seg][col] = s;
    __syncthreads();
    if (seg == 0)
        g_v[e * Hh + hbase + col] =
            red[0][col] + red[1][col] + red[2][col] + red[3][col];
}

// ---------------- CLS delta per (batch, slot) ------------------------------
__global__ void cls_kernel() {
    int b = blockIdx.x >> 1;
    int s = blockIdx.x & 1;
    int n = b * Ss;
    int e = g_sel[2*n + s];
    int r = g_slot_row[2*n + s];
    float w = g_selw[2*n + s];
    const __nv_bfloat16* hp = g_hh + (size_t)r * Hh;
    const __nv_bfloat16* lp = g_hl + (size_t)r * Hh;
    const float* vp = g_v + e * Hh;
    float acc = 0.0f;
    for (int i = threadIdx.x; i < Hh; i += blockDim.x)
        acc += (__bfloat162float(hp[i]) + __bfloat162float(lp[i])) * vp[i];
    __shared__ float red[8];
    int lane = threadIdx.x & 31, warp = threadIdx.x >> 5;
    #pragma unroll
    for (int o = 16; o > 0; o >>= 1) acc += __shfl_down_sync(0xffffffffu, acc, o);
    if (lane == 0) red[warp] = acc;
    __syncthreads();
    if (threadIdx.x == 0) {
        float t = 0.0f;
        for (int i = 0; i < (int)(blockDim.x >> 5); i++) t += red[i];
        g_cls_delta[e * Bb + b] = w * t;
    }
}

__global__ void elog_kernel(const float* __restrict__ bc, float* __restrict__ out) {
    int b = threadIdx.x;
    if (b < Bb) {
        float cum = bc[0];
        for (int e = 0; e < Ee; e++) {
            cum += g_cls_delta[e * Bb + b];
            out[OUT_ELOG + e * Bb + b] = cum;
        }
    }
}

// ---------------- launch ----------------------------------------------------
extern "C" void kernel_launch(void* const* d_in, const int* in_sizes, int n_in,
                              void* d_out, int out_size) {
    const float* x  = (const float*)d_in[0];
    const float* W1 = (const float*)d_in[2];
    const float* W2 = (const float*)d_in[3];
    const float* W3 = (const float*)d_in[4];
    const float* Wg = (const float*)d_in[5];
    const float* Wc = (const float*)d_in[6];
    const float* bc = (const float*)d_in[7];
    float* out = (float*)d_out;

    cudaFuncSetAttribute(ffn1_mma, cudaFuncAttributeMaxDynamicSharedMemorySize, FFN_SMEM);
    cudaFuncSetAttribute(ffn2_mma, cudaFuncAttributeMaxDynamicSharedMemorySize, FFN_SMEM);

    init_kernel<<<1, 64>>>();
    gating_kernel<<<Nn, 256>>>(x, Wg, out);
    scan_kernel<<<1, 1>>>();
    scatter_kernel<<<(Nn + 255) / 256, 256>>>();
    split_all_kernel<<<2048, 256>>>(x, W1, W3, W2);
    ffn1_mma<<<dim3(Nn / BM, Hh / BN, Ee), 256, FFN_SMEM>>>(x, W1, W3);
    vproj_kernel<<<dim3(Hh / 64, Ee), 256>>>(W2, Wc);
    ffn2_mma<<<dim3(Nn / BM2, Dd / BN, Ee), 256, FFN_SMEM>>>(W2);
    combine_kernel<<<1024, 256>>>(out);
    cls_kernel<<<Bb * 2, 256>>>();
    elog_kernel<<<1, 32>>>(bc, out);
}